// round 8
// baseline (speedup 1.0000x reference)
#include <cuda_runtime.h>
#include <cuda_bf16.h>
#include <mma.h>

using namespace nvcuda;

#define K_CLS 10
#define P 128
#define CAP 262144          // max rows (m)
#define EPS_C 0.01f
#define KT2 128             // rows per gram tile
#define BPC 14              // blocks per class (140 blocks <= 148 SMs, one wave)
#define LDP 132             // padded row stride (floats) for chol / epilogue smem
#define GRAM_SMEM 69632     // max(64KB tiles, 128*132*4 epilogue) rounded up

// ---------------- device globals (no allocations allowed) ----------------
__device__ __nv_bfloat16 d_xH[(size_t)CAP * P];   // 64 MB, class-sorted hi
__device__ __nv_bfloat16 d_xL[(size_t)CAP * P];   // 64 MB, class-sorted lo
__device__ int   d_count[K_CLS];
__device__ int   d_base[K_CLS];
__device__ int   d_cursor2[K_CLS];
__device__ float d_part[K_CLS * BPC][P * P];      // 9.2 MB per-block partials
__device__ float d_cov[K_CLS * P * P];            // per-class Gram
__device__ float d_covfull[P * P];                // full Gram
__device__ float d_logdets[K_CLS + 1];            // [0]=full, [1..10]=classes

// ---------------- zero small state ----------------
__global__ void zero_kernel() {
    int t = threadIdx.x;
    if (t < K_CLS) d_count[t] = 0;
    if (t < K_CLS + 1) d_logdets[t] = 0.0f;
}

// ---------------- class histogram ----------------
__global__ void hist_kernel(const int* __restrict__ y, int m) {
    __shared__ int h[K_CLS];
    if (threadIdx.x < K_CLS) h[threadIdx.x] = 0;
    __syncthreads();
    for (int i = blockIdx.x * blockDim.x + threadIdx.x; i < m;
         i += gridDim.x * blockDim.x) {
        int c = y[i];
        c = min(max(c, 0), K_CLS - 1);
        atomicAdd(&h[c], 1);
    }
    __syncthreads();
    if (threadIdx.x < K_CLS) atomicAdd(&d_count[threadIdx.x], h[threadIdx.x]);
}

// ---------------- tiny prefix scan ----------------
__global__ void prefix_kernel() {
    if (threadIdx.x == 0) {
        int acc = 0;
        for (int c = 0; c < K_CLS; c++) {
            d_base[c] = acc;
            d_cursor2[c] = acc;
            acc += d_count[c];
        }
    }
}

// ---------------- scatter + split-convert: x -> class-sorted hi/lo bf16 ------
__global__ void convert_kernel(const float* __restrict__ x,
                               const int* __restrict__ y, int m) {
    __shared__ int sCnt[K_CLS], sBase[K_CLS];
    __shared__ int sDest[256];
    int tid = threadIdx.x;
    int i = blockIdx.x * 256 + tid;
    if (tid < K_CLS) sCnt[tid] = 0;
    __syncthreads();

    int c = 0, local = 0;
    bool act = (i < m);
    if (act) {
        c = y[i];
        c = min(max(c, 0), K_CLS - 1);
        unsigned mask = __match_any_sync(__activemask(), c);
        int leader = __ffs(mask) - 1;
        int ln = tid & 31;
        int rank = __popc(mask & ((1u << ln) - 1));
        int wb = 0;
        if (ln == leader) wb = atomicAdd(&sCnt[c], __popc(mask));
        wb = __shfl_sync(mask, wb, leader);
        local = wb + rank;
    }
    __syncthreads();
    if (tid < K_CLS) sBase[tid] = atomicAdd(&d_cursor2[tid], sCnt[tid]);
    __syncthreads();
    sDest[tid] = act ? (sBase[c] + local) : 0;
    __syncthreads();

    // phase B: warp-per-row streaming convert (lane = one float4 of the row)
    int w = tid >> 5, ln = tid & 31;
    for (int rr = 0; rr < 32; rr++) {
        int l = w * 32 + rr;
        int g = blockIdx.x * 256 + l;
        if (g >= m) break;
        int dest = sDest[l];
        float4 v = reinterpret_cast<const float4*>(x)[g * 32 + ln];
        __nv_bfloat16 hx = __float2bfloat16_rn(v.x);
        __nv_bfloat16 hy = __float2bfloat16_rn(v.y);
        __nv_bfloat16 hz = __float2bfloat16_rn(v.z);
        __nv_bfloat16 hw = __float2bfloat16_rn(v.w);
        __nv_bfloat16 lx = __float2bfloat16_rn(v.x - __bfloat162float(hx));
        __nv_bfloat16 ly = __float2bfloat16_rn(v.y - __bfloat162float(hy));
        __nv_bfloat16 lz = __float2bfloat16_rn(v.z - __bfloat162float(hz));
        __nv_bfloat16 lw = __float2bfloat16_rn(v.w - __bfloat162float(hw));
        __nv_bfloat162 h0(hx, hy), h1(hz, hw), l0(lx, ly), l1(lz, lw);
        uint2 uh, ul;
        uh.x = *reinterpret_cast<unsigned*>(&h0);
        uh.y = *reinterpret_cast<unsigned*>(&h1);
        ul.x = *reinterpret_cast<unsigned*>(&l0);
        ul.y = *reinterpret_cast<unsigned*>(&l1);
        reinterpret_cast<uint2*>(d_xH)[(size_t)dest * 32 + ln] = uh;
        reinterpret_cast<uint2*>(d_xL)[(size_t)dest * 32 + ln] = ul;
    }
}

// ---------------- dense per-class Gram, split-bf16 wmma, partials out --------
// cov_partial = H^T H + H^T L + (H^T L)^T  assembled per block in smem,
// written to d_part (no global atomics, deterministic reduce later).
__global__ void __launch_bounds__(512, 1)
gram_kernel() {
    extern __shared__ char smraw[];
    __nv_bfloat16 (*sH)[P] = reinterpret_cast<__nv_bfloat16(*)[P]>(smraw);
    __nv_bfloat16 (*sL)[P] = reinterpret_cast<__nv_bfloat16(*)[P]>(smraw + 32768);

    int c = blockIdx.y;
    int n = d_count[c];
    int base = d_base[c];

    int tid = threadIdx.x;
    int w = tid >> 5;
    int wr = w & 7;        // output row strip
    int wc = w >> 3;       // column half

    wmma::fragment<wmma::matrix_a, 16, 16, 16, __nv_bfloat16, wmma::col_major> faH;
    wmma::fragment<wmma::matrix_b, 16, 16, 16, __nv_bfloat16, wmma::row_major> fbH, fbL;
    wmma::fragment<wmma::accumulator, 16, 16, 16, float> accH[4], accL[4];
#pragma unroll
    for (int t = 0; t < 4; t++) {
        wmma::fill_fragment(accH[t], 0.0f);
        wmma::fill_fragment(accL[t], 0.0f);
    }

    for (int r0 = blockIdx.x * KT2; r0 < n; r0 += BPC * KT2) {
        __syncthreads();
        // load 128 rows x 256B from each of H/L: 4096 uint4, 8 per thread
#pragma unroll
        for (int q = 0; q < 8; q++) {
            int u = tid + q * 512;
            int idx = u & 2047;
            int row = idx >> 4, seg = idx & 15;
            uint4 val = make_uint4(0u, 0u, 0u, 0u);
            if (u < 2048) {
                if (r0 + row < n)
                    val = reinterpret_cast<const uint4*>(d_xH)
                              [(size_t)(base + r0 + row) * 16 + seg];
                reinterpret_cast<uint4*>(sH)[idx] = val;
            } else {
                if (r0 + row < n)
                    val = reinterpret_cast<const uint4*>(d_xL)
                              [(size_t)(base + r0 + row) * 16 + seg];
                reinterpret_cast<uint4*>(sL)[idx] = val;
            }
        }
        __syncthreads();
#pragma unroll
        for (int ks = 0; ks < 8; ks++) {
            wmma::load_matrix_sync(faH, &sH[ks * 16][wr * 16], P);
#pragma unroll
            for (int t = 0; t < 4; t++) {
                int tc = wc * 64 + t * 16;
                wmma::load_matrix_sync(fbH, &sH[ks * 16][tc], P);
                wmma::load_matrix_sync(fbL, &sL[ks * 16][tc], P);
                wmma::mma_sync(accH[t], faH, fbH, accH[t]);
                wmma::mma_sync(accL[t], faH, fbL, accL[t]);
            }
        }
    }

    // epilogue: assemble C1 + C2 + C2^T in smem, write one partial
    __syncthreads();
    float* M = reinterpret_cast<float*>(smraw);   // [128][LDP]
#pragma unroll
    for (int t = 0; t < 4; t++)
        wmma::store_matrix_sync(&M[(wr * 16) * LDP + wc * 64 + t * 16],
                                accH[t], LDP, wmma::mem_row_major);
    __syncthreads();
    float c1v[32];
#pragma unroll
    for (int k = 0; k < 32; k++) {
        int e = k * 512 + tid;
        c1v[k] = M[(e >> 7) * LDP + (e & 127)];
    }
    __syncthreads();
#pragma unroll
    for (int t = 0; t < 4; t++)
        wmma::store_matrix_sync(&M[(wr * 16) * LDP + wc * 64 + t * 16],
                                accL[t], LDP, wmma::mem_row_major);
    __syncthreads();
    float* out = d_part[c * BPC + blockIdx.x];
#pragma unroll
    for (int k = 0; k < 32; k++) {
        int e = k * 512 + tid;
        int r = e >> 7, cc = e & 127;
        out[e] = c1v[k] + M[r * LDP + cc] + M[cc * LDP + r];
    }
}

// ---------------- deterministic reductions (double accumulation) -------------
__global__ void reduce_kernel() {
    int e = blockIdx.x * 256 + threadIdx.x;
    if (e >= K_CLS * P * P) return;
    int c = e / (P * P), j = e % (P * P);
    double s = 0.0;
#pragma unroll
    for (int b = 0; b < BPC; b++) s += (double)d_part[c * BPC + b][j];
    d_cov[e] = (float)s;
}

__global__ void fullsum_kernel() {
    int j = blockIdx.x * 256 + threadIdx.x;
    if (j >= P * P) return;
    double s = 0.0;
    for (int cb = 0; cb < K_CLS * BPC; cb++) s += (double)d_part[cb][j];
    d_covfull[j] = (float)s;
}

// ---------------- Cholesky logdet (one block per matrix) ----------------
__global__ void __launch_bounds__(128) chol_kernel(int m) {
    extern __shared__ float A[];  // 128*LDP floats
    __shared__ float sDiag;
    int b = blockIdx.x;
    int i = threadIdx.x;          // thread == row

    if (b == 0) {
        float scal = (float)P / ((float)m * EPS_C);
        for (int e = i; e < P * P; e += 128)
            A[(e >> 7) * LDP + (e & 127)] =
                ((e % (P + 1)) == 0 ? 1.0f : 0.0f) + scal * d_covfull[e];
    } else {
        int c = b - 1;
        int n = d_count[c];
        int ns = n > 0 ? n : 1;
        float scal = (float)P / ((float)ns * EPS_C);
        for (int e = i; e < P * P; e += 128)
            A[(e >> 7) * LDP + (e & 127)] =
                ((e % (P + 1)) == 0 ? 1.0f : 0.0f) + scal * d_cov[c * P * P + e];
    }
    __syncthreads();

    float logsum = 0.0f;
    for (int j = 0; j < P; j++) {
        float s = 0.0f;
        if (i >= j) {
            const float4* ri = reinterpret_cast<const float4*>(A + i * LDP);
            const float4* rj = reinterpret_cast<const float4*>(A + j * LDP);
            float a0 = 0.f, a1 = 0.f, a2 = 0.f, a3 = 0.f;
            int n4 = j >> 2;
#pragma unroll 4
            for (int t = 0; t < n4; t++) {
                float4 u = ri[t];
                float4 v = rj[t];
                a0 += u.x * v.x; a1 += u.y * v.y;
                a2 += u.z * v.z; a3 += u.w * v.w;
            }
            for (int t = n4 * 4; t < j; t++)
                a0 += A[i * LDP + t] * A[j * LDP + t];
            s = A[i * LDP + j] - ((a0 + a1) + (a2 + a3));
            if (i == j) sDiag = s;
        }
        __syncthreads();
        float dd = sDiag;
        float d = sqrtf(dd);
        if (i == 0) logsum += 0.5f * logf(dd);
        if (i > j)       A[i * LDP + j] = s / d;
        else if (i == j) A[i * LDP + j] = d;
        __syncthreads();
    }
    if (i == 0) d_logdets[b] = logsum;   // = slogdet/2
}

// ---------------- final reduction to 4 scalars ----------------
__global__ void finalize_kernel(float* __restrict__ out, int m) {
    if (threadIdx.x == 0 && blockIdx.x == 0) {
        float disc = d_logdets[0];   // discrimn_empi == discrimn_theo (GAM1 = 1)
        float comp = 0.0f;
#pragma unroll
        for (int c = 0; c < K_CLS; c++) {
            int n = d_count[c];
            if (n > 0) comp += d_logdets[1 + c] * ((float)n / (float)m);
        }
        out[0] = -disc + comp;  // GAM2 = 1
        out[1] = disc;
        out[2] = disc;
        out[3] = comp;
    }
}

// ---------------- launch ----------------
extern "C" void kernel_launch(void* const* d_in, const int* in_sizes, int n_in,
                              void* d_out, int out_size) {
    const float* x = (const float*)d_in[0];
    const int*   y = (const int*)d_in[1];
    int m = in_sizes[0] / P;

    cudaFuncSetAttribute(gram_kernel,
                         cudaFuncAttributeMaxDynamicSharedMemorySize, GRAM_SMEM);
    cudaFuncSetAttribute(chol_kernel,
                         cudaFuncAttributeMaxDynamicSharedMemorySize, 128 * LDP * 4);

    zero_kernel<<<1, 32>>>();
    hist_kernel<<<256, 256>>>(y, m);
    prefix_kernel<<<1, 32>>>();
    convert_kernel<<<(m + 255) / 256, 256>>>(x, y, m);
    gram_kernel<<<dim3(BPC, K_CLS), 512, GRAM_SMEM>>>();
    reduce_kernel<<<(K_CLS * P * P + 255) / 256, 256>>>();
    fullsum_kernel<<<(P * P + 255) / 256, 256>>>();
    chol_kernel<<<K_CLS + 1, P, 128 * LDP * 4>>>(m);
    finalize_kernel<<<1, 32>>>((float*)d_out, m);
}

// round 10
// speedup vs baseline: 1.4618x; 1.4618x over previous
#include <cuda_runtime.h>
#include <cuda_bf16.h>
#include <cstdint>

#define K_CLS 10
#define P 128
#define CAP 262144          // max rows (m)
#define EPS_C 0.01f
#define KT 64               // rows per gram tile
#define BPC 14              // blocks per class (140 blocks <= 148 SMs, one wave)

// ---------------- device globals (no allocations allowed) ----------------
__device__ int   d_cursor[K_CLS];              // per-class counts / cursors
__device__ int   d_idx[K_CLS * CAP];           // per-class row index lists
__device__ float d_part[K_CLS * BPC][P * P];   // per-block Gram partials
__device__ float d_cov[K_CLS * P * P];         // per-class Gram
__device__ float d_covfull[P * P];             // full Gram
__device__ float d_logdets[K_CLS + 1];         // [0]=full, [1..10]=classes

// ---------------- packed f32x2 helpers (sm_100+ PTX, non-'a' target OK) ------
__device__ __forceinline__ void fma2(unsigned long long& d,
                                     unsigned long long a,
                                     unsigned long long b) {
    asm("fma.rn.f32x2 %0, %1, %2, %0;" : "+l"(d) : "l"(a), "l"(b));
}
__device__ __forceinline__ unsigned long long dup2(float x) {
    unsigned long long r;
    asm("mov.b64 %0, {%1, %1};" : "=l"(r) : "f"(x));
    return r;
}

// ---------------- zero small state ----------------
__global__ void zero_kernel() {
    int t = threadIdx.x;
    if (t < K_CLS) d_cursor[t] = 0;
    if (t < K_CLS + 1) d_logdets[t] = 0.0f;
}

// ---------------- class-partition scatter (index lists + counts) ----------------
__global__ void scatter_kernel(const int* __restrict__ y, int m) {
    __shared__ int sCnt[K_CLS], sBase[K_CLS];
    int tid = threadIdx.x;
    int i = blockIdx.x * blockDim.x + tid;
    if (tid < K_CLS) sCnt[tid] = 0;
    __syncthreads();

    int c = 0, local = 0;
    bool act = (i < m);
    if (act) {
        c = y[i];
        c = min(max(c, 0), K_CLS - 1);
        unsigned mask = __match_any_sync(__activemask(), c);
        int leader = __ffs(mask) - 1;
        int lane = tid & 31;
        int rank = __popc(mask & ((1u << lane) - 1));
        int wb = 0;
        if (lane == leader) wb = atomicAdd(&sCnt[c], __popc(mask));
        wb = __shfl_sync(mask, wb, leader);
        local = wb + rank;
    }
    __syncthreads();
    if (tid < K_CLS) sBase[tid] = atomicAdd(&d_cursor[tid], sCnt[tid]);
    __syncthreads();
    if (act) d_idx[c * CAP + sBase[c] + local] = i;
}

// ---------------- exact fp32 Gram via packed f32x2 FFMA ----------------
// Block (bx, c): partial C = sum over its row-slice of x_row outer x_row.
// 256 threads, 8x8 micro-tile each (tx: cols, ty: rows), f32x2 accumulators.
// KT=64-row tile in smem; next tile register-prefetched during compute.
__global__ void __launch_bounds__(256, 1)
gram_kernel(const float* __restrict__ x) {
    __shared__ float tile[KT * P];     // 32 KB
    int tid = threadIdx.x;
    int tx = tid & 15;                 // col group: cols [8*tx, 8*tx+8)
    int ty = tid >> 4;                 // row group: rows [8*ty, 8*ty+8)
    int c = blockIdx.y;
    int n = d_cursor[c];
    const int* idx = d_idx + c * CAP;

    unsigned long long acc[8][4];
#pragma unroll
    for (int r = 0; r < 8; r++)
#pragma unroll
        for (int p = 0; p < 4; p++) acc[r][p] = 0ull;

    int j0 = blockIdx.x * KT;
    if (j0 < n) {
        // load first tile (row = u>>5 in [0,64), seg = u&31; 512B/row coalesced)
#pragma unroll
        for (int q = 0; q < 8; q++) {
            int u = tid + q * 256;
            int row = u >> 5, seg = u & 31;
            uint4 v = make_uint4(0u, 0u, 0u, 0u);
            if (j0 + row < n)
                v = reinterpret_cast<const uint4*>(x)[(size_t)idx[j0 + row] * 32 + seg];
            reinterpret_cast<uint4*>(tile)[u] = v;
        }
        __syncthreads();

        for (; j0 < n; ) {
            int jn = j0 + BPC * KT;
            // prefetch next tile into registers (overlaps FMA phase)
            uint4 pf[8];
#pragma unroll
            for (int q = 0; q < 8; q++) {
                int u = tid + q * 256;
                int row = u >> 5, seg = u & 31;
                pf[q] = make_uint4(0u, 0u, 0u, 0u);
                if (jn + row < n && jn < n)
                    pf[q] = reinterpret_cast<const uint4*>(x)
                                [(size_t)idx[jn + row] * 32 + seg];
            }
            // compute: rank-KT update, packed f32x2
#pragma unroll 2
            for (int k = 0; k < KT; k++) {
                const float* rowk = tile + k * P;
                float4 a0 = *reinterpret_cast<const float4*>(rowk + ty * 8);
                float4 a1 = *reinterpret_cast<const float4*>(rowk + ty * 8 + 4);
                ulonglong2 b0 = *reinterpret_cast<const ulonglong2*>(rowk + tx * 8);
                ulonglong2 b1 = *reinterpret_cast<const ulonglong2*>(rowk + tx * 8 + 4);
                unsigned long long ad[8];
                ad[0] = dup2(a0.x); ad[1] = dup2(a0.y);
                ad[2] = dup2(a0.z); ad[3] = dup2(a0.w);
                ad[4] = dup2(a1.x); ad[5] = dup2(a1.y);
                ad[6] = dup2(a1.z); ad[7] = dup2(a1.w);
#pragma unroll
                for (int r = 0; r < 8; r++) {
                    fma2(acc[r][0], ad[r], b0.x);
                    fma2(acc[r][1], ad[r], b0.y);
                    fma2(acc[r][2], ad[r], b1.x);
                    fma2(acc[r][3], ad[r], b1.y);
                }
            }
            __syncthreads();
            // commit prefetched tile
#pragma unroll
            for (int q = 0; q < 8; q++)
                reinterpret_cast<uint4*>(tile)[tid + q * 256] = pf[q];
            __syncthreads();
            j0 = jn;
        }
    }

    // write partial (always, so reduce sees defined data)
    float* out = d_part[c * BPC + blockIdx.x];
#pragma unroll
    for (int r = 0; r < 8; r++) {
#pragma unroll
        for (int p = 0; p < 4; p++)
            *reinterpret_cast<unsigned long long*>(
                &out[(ty * 8 + r) * P + tx * 8 + p * 2]) = acc[r][p];
    }
}

// ---------------- deterministic reductions (double accumulation) -------------
__global__ void reduce_kernel() {
    int e = blockIdx.x * 256 + threadIdx.x;
    if (e >= K_CLS * P * P) return;
    int c = e / (P * P), j = e % (P * P);
    double s = 0.0;
#pragma unroll
    for (int b = 0; b < BPC; b++) s += (double)d_part[c * BPC + b][j];
    d_cov[e] = (float)s;
}

__global__ void fullsum_kernel() {
    int j = blockIdx.x * 256 + threadIdx.x;
    if (j >= P * P) return;
    double s = 0.0;
    for (int cb = 0; cb < K_CLS * BPC; cb++) s += (double)d_part[cb][j];
    d_covfull[j] = (float)s;
}

// ---------------- Cholesky logdet (round-2 col-major form) ----------------
__global__ void chol_kernel(int m) {
    extern __shared__ float A[];  // 128*128 floats = 64 KB
    int b = blockIdx.x;
    int i = threadIdx.x;          // 128 threads, thread == row

    if (b == 0) {
        float scal = (float)P / ((float)m * EPS_C);
        for (int e = i; e < P * P; e += 128)
            A[e] = ((e % (P + 1)) == 0 ? 1.0f : 0.0f) + scal * d_covfull[e];
    } else {
        int c = b - 1;
        int n = d_cursor[c];
        int ns = n > 0 ? n : 1;
        float scal = (float)P / ((float)ns * EPS_C);
        for (int e = i; e < P * P; e += 128)
            A[e] = ((e % (P + 1)) == 0 ? 1.0f : 0.0f) + scal * d_cov[c * P * P + e];
    }
    __syncthreads();

    float logsum = 0.0f;
    for (int j = 0; j < P; j++) {
        float s = 0.0f;
        if (i >= j) {
            s = A[j * P + i];
            float a0 = 0.f, a1 = 0.f, a2 = 0.f, a3 = 0.f;
            int t = 0;
            for (; t + 3 < j; t += 4) {
                a0 += A[(t + 0) * P + i] * A[(t + 0) * P + j];
                a1 += A[(t + 1) * P + i] * A[(t + 1) * P + j];
                a2 += A[(t + 2) * P + i] * A[(t + 2) * P + j];
                a3 += A[(t + 3) * P + i] * A[(t + 3) * P + j];
            }
            for (; t < j; t++) a0 += A[t * P + i] * A[t * P + j];
            s -= (a0 + a1) + (a2 + a3);
            A[j * P + i] = s;
        }
        __syncthreads();
        float d = sqrtf(A[j * P + j]);
        logsum += logf(d);
        if (i > j)       A[j * P + i] = s / d;
        else if (i == j) A[j * P + i] = d;
        __syncthreads();
    }
    if (i == 0) d_logdets[b] = logsum;   // = slogdet/2
}

// ---------------- final reduction to 4 scalars ----------------
__global__ void finalize_kernel(float* __restrict__ out, int m) {
    if (threadIdx.x == 0 && blockIdx.x == 0) {
        float disc = d_logdets[0];   // discrimn_empi == discrimn_theo (GAM1 = 1)
        float comp = 0.0f;
#pragma unroll
        for (int c = 0; c < K_CLS; c++) {
            int n = d_cursor[c];
            if (n > 0) comp += d_logdets[1 + c] * ((float)n / (float)m);
        }
        out[0] = -disc + comp;  // GAM2 = 1
        out[1] = disc;
        out[2] = disc;
        out[3] = comp;
    }
}

// ---------------- launch ----------------
extern "C" void kernel_launch(void* const* d_in, const int* in_sizes, int n_in,
                              void* d_out, int out_size) {
    const float* x = (const float*)d_in[0];
    const int*   y = (const int*)d_in[1];
    int m = in_sizes[0] / P;

    cudaFuncSetAttribute(chol_kernel,
                         cudaFuncAttributeMaxDynamicSharedMemorySize, 65536);

    zero_kernel<<<1, 32>>>();
    scatter_kernel<<<(m + 255) / 256, 256>>>(y, m);
    gram_kernel<<<dim3(BPC, K_CLS), 256>>>(x);
    reduce_kernel<<<(K_CLS * P * P + 255) / 256, 256>>>();
    fullsum_kernel<<<(P * P + 255) / 256, 256>>>();
    chol_kernel<<<K_CLS + 1, P, 65536>>>(m);
    finalize_kernel<<<1, 32>>>((float*)d_out, m);
}

// round 11
// speedup vs baseline: 1.5339x; 1.0493x over previous
#include <cuda_runtime.h>
#include <cuda_bf16.h>
#include <cstdint>

#define K_CLS 10
#define P 128
#define CAP 262144          // max rows (m)
#define EPS_C 0.01f
#define KT 64               // rows per gram tile
#define BPC 29              // blocks per class (290 blocks -> 2 per SM)

// ---------------- device globals (no allocations allowed) ----------------
__device__ int   d_cursor[K_CLS];              // per-class counts / cursors
__device__ int   d_idx[K_CLS * CAP];           // per-class row index lists
__device__ float d_part[K_CLS * BPC][P * P];   // per-block Gram partials
__device__ float d_cov[K_CLS * P * P];         // per-class Gram
__device__ float d_logdets[K_CLS + 1];         // [0]=full, [1..10]=classes

// ---------------- packed f32x2 helpers ----------------
__device__ __forceinline__ void fma2(unsigned long long& d,
                                     unsigned long long a,
                                     unsigned long long b) {
    asm("fma.rn.f32x2 %0, %1, %2, %0;" : "+l"(d) : "l"(a), "l"(b));
}
__device__ __forceinline__ unsigned long long dup2(float x) {
    unsigned long long r;
    asm("mov.b64 %0, {%1, %1};" : "=l"(r) : "f"(x));
    return r;
}
__device__ __forceinline__ void cp16(uint32_t saddr, const void* gaddr, int sz) {
    asm volatile("cp.async.cg.shared.global [%0], [%1], 16, %2;"
                 :: "r"(saddr), "l"(gaddr), "r"(sz));
}
__device__ __forceinline__ void cp_commit() {
    asm volatile("cp.async.commit_group;");
}
__device__ __forceinline__ void cp_wait1() {
    asm volatile("cp.async.wait_group 1;");
}
__device__ __forceinline__ void cp_wait0() {
    asm volatile("cp.async.wait_group 0;");
}

// ---------------- zero small state ----------------
__global__ void zero_kernel() {
    int t = threadIdx.x;
    if (t < K_CLS) d_cursor[t] = 0;
    if (t < K_CLS + 1) d_logdets[t] = 0.0f;
}

// ---------------- class-partition scatter (index lists + counts) ----------------
__global__ void scatter_kernel(const int* __restrict__ y, int m) {
    __shared__ int sCnt[K_CLS], sBase[K_CLS];
    int tid = threadIdx.x;
    int i = blockIdx.x * blockDim.x + tid;
    if (tid < K_CLS) sCnt[tid] = 0;
    __syncthreads();

    int c = 0, local = 0;
    bool act = (i < m);
    if (act) {
        c = y[i];
        c = min(max(c, 0), K_CLS - 1);
        unsigned mask = __match_any_sync(__activemask(), c);
        int leader = __ffs(mask) - 1;
        int lane = tid & 31;
        int rank = __popc(mask & ((1u << lane) - 1));
        int wb = 0;
        if (lane == leader) wb = atomicAdd(&sCnt[c], __popc(mask));
        wb = __shfl_sync(mask, wb, leader);
        local = wb + rank;
    }
    __syncthreads();
    if (tid < K_CLS) sBase[tid] = atomicAdd(&d_cursor[tid], sCnt[tid]);
    __syncthreads();
    if (act) d_idx[c * CAP + sBase[c] + local] = i;
}

// ---------------- exact fp32 Gram: f32x2 FFMA + cp.async double-buffer -------
// 256 threads, 8x8 micro-tile each; KT=64-row tile; 2 blocks/SM.
__global__ void __launch_bounds__(256, 2)
gram_kernel(const float* __restrict__ x) {
    extern __shared__ float tile[];    // 2 x KT*P floats (64 KB)
    int tid = threadIdx.x;
    int lane = tid & 31, warp = tid >> 5;
    int tx = tid & 15;                 // col group: cols [8*tx, 8*tx+8)
    int ty = tid >> 4;                 // row group: rows [8*ty, 8*ty+8)
    int c = blockIdx.y;
    int n = d_cursor[c];
    const int* idx = d_idx + c * CAP;
    const int stride = BPC * KT;

    unsigned long long acc[8][4];
#pragma unroll
    for (int r = 0; r < 8; r++)
#pragma unroll
        for (int p = 0; p < 4; p++) acc[r][p] = 0ull;

    uint32_t sbase = (uint32_t)__cvta_generic_to_shared(tile);

    // issue async copy of one tile into buffer buf
    auto issue = [&](int j0, int buf) {
        uint32_t dst = sbase + (uint32_t)buf * (KT * P * 4);
#pragma unroll
        for (int q = 0; q < 8; q++) {
            int row = q * 8 + warp;
            int gr = j0 + row;
            const float4* src = reinterpret_cast<const float4*>(x);
            int sz = 0;
            if (gr < n) {
                src = reinterpret_cast<const float4*>(x)
                      + (size_t)idx[gr] * 32 + lane;
                sz = 16;
            }
            cp16(dst + (uint32_t)(row * P + lane * 4) * 4, src, sz);
        }
        cp_commit();
    };

    int j0 = blockIdx.x * KT;
    if (j0 < n) {
        issue(j0, 0);
        int buf = 0;
        for (; j0 < n; ) {
            int jn = j0 + stride;
            if (jn < n) { issue(jn, buf ^ 1); cp_wait1(); }
            else cp_wait0();
            __syncthreads();               // tile[buf] visible to all

            const float* tb = tile + buf * (KT * P);
#pragma unroll 2
            for (int k = 0; k < KT; k++) {
                const float* rowk = tb + k * P;
                float4 a0 = *reinterpret_cast<const float4*>(rowk + ty * 8);
                float4 a1 = *reinterpret_cast<const float4*>(rowk + ty * 8 + 4);
                ulonglong2 b0 = *reinterpret_cast<const ulonglong2*>(rowk + tx * 8);
                ulonglong2 b1 = *reinterpret_cast<const ulonglong2*>(rowk + tx * 8 + 4);
                unsigned long long ad[8];
                ad[0] = dup2(a0.x); ad[1] = dup2(a0.y);
                ad[2] = dup2(a0.z); ad[3] = dup2(a0.w);
                ad[4] = dup2(a1.x); ad[5] = dup2(a1.y);
                ad[6] = dup2(a1.z); ad[7] = dup2(a1.w);
#pragma unroll
                for (int r = 0; r < 8; r++) {
                    fma2(acc[r][0], ad[r], b0.x);
                    fma2(acc[r][1], ad[r], b0.y);
                    fma2(acc[r][2], ad[r], b1.x);
                    fma2(acc[r][3], ad[r], b1.y);
                }
            }
            __syncthreads();               // done reading tile[buf] before reuse
            buf ^= 1;
            j0 = jn;
        }
    }

    float* out = d_part[c * BPC + blockIdx.x];
#pragma unroll
    for (int r = 0; r < 8; r++) {
#pragma unroll
        for (int p = 0; p < 4; p++)
            *reinterpret_cast<unsigned long long*>(
                &out[(ty * 8 + r) * P + tx * 8 + p * 2]) = acc[r][p];
    }
}

// ---------------- deterministic reduction (double accumulation) -------------
__global__ void reduce_kernel() {
    int e = blockIdx.x * 256 + threadIdx.x;
    if (e >= K_CLS * P * P) return;
    int c = e / (P * P), j = e % (P * P);
    double s = 0.0;
#pragma unroll
    for (int b = 0; b < BPC; b++) s += (double)d_part[c * BPC + b][j];
    d_cov[e] = (float)s;
}

// ---------------- Cholesky logdet, 2 columns per barrier pair ---------------
// Col-major A[col*P + row]. Left-looking; columns j, j+1 share own-row loads;
// col j+1's missing t=j term fixed up in registers after col j resolves.
__global__ void chol_kernel(int m) {
    extern __shared__ float A[];  // 128*128 floats = 64 KB
    __shared__ float sd[3];       // [0]=s0@row j, [1]=s0@row j+1, [2]=s1@row j+1
    int b = blockIdx.x;
    int i = threadIdx.x;          // thread == row

    if (b == 0) {
        // full cov = sum of class covs (consistent with per-class matrices)
        float scal = (float)P / ((float)m * EPS_C);
        for (int e = i; e < P * P; e += 128) {
            float v = 0.f;
#pragma unroll
            for (int c = 0; c < K_CLS; c++) v += d_cov[c * P * P + e];
            A[e] = ((e % (P + 1)) == 0 ? 1.0f : 0.0f) + scal * v;
        }
    } else {
        int c = b - 1;
        int n = d_cursor[c];
        int ns = n > 0 ? n : 1;
        float scal = (float)P / ((float)ns * EPS_C);
        for (int e = i; e < P * P; e += 128)
            A[e] = ((e % (P + 1)) == 0 ? 1.0f : 0.0f) + scal * d_cov[c * P * P + e];
    }
    __syncthreads();

    float logsum = 0.0f;
    for (int j = 0; j < P; j += 2) {
        float s0 = 0.0f, s1 = 0.0f;
        if (i >= j) {
            s0 = A[j * P + i];
            s1 = A[(j + 1) * P + i];
            float a00 = 0.f, a01 = 0.f, a10 = 0.f, a11 = 0.f;
            int t = 0;
            for (; t + 1 < j; t += 2) {
                float u0 = A[t * P + i], u1 = A[(t + 1) * P + i];
                a00 += u0 * A[t * P + j];
                a01 += u1 * A[(t + 1) * P + j];
                a10 += u0 * A[t * P + j + 1];
                a11 += u1 * A[(t + 1) * P + j + 1];
            }
            if (t < j) {
                float u = A[t * P + i];
                a00 += u * A[t * P + j];
                a10 += u * A[t * P + j + 1];
            }
            s0 -= a00 + a01;
            s1 -= a10 + a11;
            if (i == j) sd[0] = s0;
            if (i == j + 1) { sd[1] = s0; sd[2] = s1; }
        }
        __syncthreads();
        float d0 = sqrtf(sd[0]);
        float Lj1 = sd[1] / d0;             // L[j+1][j]
        float d1 = sqrtf(sd[2] - Lj1 * Lj1);
        logsum += logf(d0) + logf(d1);
        if (i == j) {
            A[j * P + i] = d0;
        } else if (i == j + 1) {
            A[j * P + i] = Lj1;
            A[(j + 1) * P + i] = d1;
        } else if (i > j + 1) {
            float L0 = s0 / d0;
            A[j * P + i] = L0;
            A[(j + 1) * P + i] = (s1 - L0 * Lj1) / d1;
        }
        __syncthreads();
    }
    if (i == 0) d_logdets[b] = logsum;   // = slogdet/2
}

// ---------------- final reduction to 4 scalars ----------------
__global__ void finalize_kernel(float* __restrict__ out, int m) {
    if (threadIdx.x == 0 && blockIdx.x == 0) {
        float disc = d_logdets[0];   // discrimn_empi == discrimn_theo (GAM1 = 1)
        float comp = 0.0f;
#pragma unroll
        for (int c = 0; c < K_CLS; c++) {
            int n = d_cursor[c];
            if (n > 0) comp += d_logdets[1 + c] * ((float)n / (float)m);
        }
        out[0] = -disc + comp;  // GAM2 = 1
        out[1] = disc;
        out[2] = disc;
        out[3] = comp;
    }
}

// ---------------- launch ----------------
extern "C" void kernel_launch(void* const* d_in, const int* in_sizes, int n_in,
                              void* d_out, int out_size) {
    const float* x = (const float*)d_in[0];
    const int*   y = (const int*)d_in[1];
    int m = in_sizes[0] / P;

    cudaFuncSetAttribute(gram_kernel,
                         cudaFuncAttributeMaxDynamicSharedMemorySize, 2 * KT * P * 4);
    cudaFuncSetAttribute(chol_kernel,
                         cudaFuncAttributeMaxDynamicSharedMemorySize, 65536);

    zero_kernel<<<1, 32>>>();
    scatter_kernel<<<(m + 255) / 256, 256>>>(y, m);
    gram_kernel<<<dim3(BPC, K_CLS), 256, 2 * KT * P * 4>>>(x);
    reduce_kernel<<<(K_CLS * P * P + 255) / 256, 256>>>();
    chol_kernel<<<K_CLS + 1, P, 65536>>>(m);
    finalize_kernel<<<1, 32>>>((float*)d_out, m);
}

// round 12
// speedup vs baseline: 1.5591x; 1.0164x over previous
#include <cuda_runtime.h>
#include <cuda_bf16.h>
#include <cstdint>

#define K_CLS 10
#define P 128
#define CAP 262144          // max rows (m)
#define EPS_C 0.01f
#define KT 64               // rows per gram tile
#define BPC 29              // blocks per class (290 blocks -> 2 per SM)
#define NTHREADS 160        // gram block size (136 compute + loaders)
#define NT_ACT 136          // lower-triangle 8x8 tiles of 16x16 grid

// ---------------- device globals (no allocations allowed) ----------------
__device__ int   d_cursor[K_CLS];              // per-class counts / cursors
__device__ int   d_idx[K_CLS * CAP];           // per-class row index lists
__device__ float d_part[K_CLS * BPC][P * P];   // per-block Gram partials (lower tiles)
__device__ float d_cov[K_CLS * P * P];         // per-class Gram (full, mirrored)
__device__ float d_logdets[K_CLS + 1];         // [0]=full, [1..10]=classes

// ---------------- packed f32x2 helpers ----------------
__device__ __forceinline__ void fma2(unsigned long long& d,
                                     unsigned long long a,
                                     unsigned long long b) {
    asm("fma.rn.f32x2 %0, %1, %2, %0;" : "+l"(d) : "l"(a), "l"(b));
}
__device__ __forceinline__ unsigned long long dup2(float x) {
    unsigned long long r;
    asm("mov.b64 %0, {%1, %1};" : "=l"(r) : "f"(x));
    return r;
}
__device__ __forceinline__ void cp16(uint32_t saddr, const void* gaddr, int sz) {
    asm volatile("cp.async.cg.shared.global [%0], [%1], 16, %2;"
                 :: "r"(saddr), "l"(gaddr), "r"(sz));
}
__device__ __forceinline__ void cp_commit() { asm volatile("cp.async.commit_group;"); }
__device__ __forceinline__ void cp_wait1()  { asm volatile("cp.async.wait_group 1;"); }
__device__ __forceinline__ void cp_wait0()  { asm volatile("cp.async.wait_group 0;"); }

// ---------------- zero small state ----------------
__global__ void zero_kernel() {
    int t = threadIdx.x;
    if (t < K_CLS) d_cursor[t] = 0;
    if (t < K_CLS + 1) d_logdets[t] = 0.0f;
}

// ---------------- class-partition scatter (index lists + counts) ----------------
__global__ void scatter_kernel(const int* __restrict__ y, int m) {
    __shared__ int sCnt[K_CLS], sBase[K_CLS];
    int tid = threadIdx.x;
    int i = blockIdx.x * blockDim.x + tid;
    if (tid < K_CLS) sCnt[tid] = 0;
    __syncthreads();

    int c = 0, local = 0;
    bool act = (i < m);
    if (act) {
        c = y[i];
        c = min(max(c, 0), K_CLS - 1);
        unsigned mask = __match_any_sync(__activemask(), c);
        int leader = __ffs(mask) - 1;
        int lane = tid & 31;
        int rank = __popc(mask & ((1u << lane) - 1));
        int wb = 0;
        if (lane == leader) wb = atomicAdd(&sCnt[c], __popc(mask));
        wb = __shfl_sync(mask, wb, leader);
        local = wb + rank;
    }
    __syncthreads();
    if (tid < K_CLS) sBase[tid] = atomicAdd(&d_cursor[tid], sCnt[tid]);
    __syncthreads();
    if (act) d_idx[c * CAP + sBase[c] + local] = i;
}

// ---------------- exact fp32 Gram, symmetric (lower triangle only) ----------
// 160 threads; threads 0..135 each own one 8x8 micro-tile of the lower
// triangle (incl. diagonal) of the 16x16 tile grid. f32x2 accumulators,
// KT=64-row smem tile, cp.async double-buffer, 2 blocks/SM.
__global__ void __launch_bounds__(NTHREADS, 2)
gram_kernel(const float* __restrict__ x) {
    extern __shared__ float tile[];    // 2 x KT*P floats (64 KB)
    int tid = threadIdx.x;
    int c = blockIdx.y;
    int n = d_cursor[c];
    const int* idx = d_idx + c * CAP;
    const int stride = BPC * KT;

    // map tid -> lower-triangle tile (tr, tc), tc <= tr
    int tr = 0, tc = 0;
    if (tid < NT_ACT) {
        tr = (int)((sqrtf(8.0f * (float)tid + 1.0f) - 1.0f) * 0.5f);
        while ((tr + 1) * (tr + 2) / 2 <= tid) tr++;
        while (tr * (tr + 1) / 2 > tid) tr--;
        tc = tid - tr * (tr + 1) / 2;
    }

    unsigned long long acc[8][4];
#pragma unroll
    for (int r = 0; r < 8; r++)
#pragma unroll
        for (int p = 0; p < 4; p++) acc[r][p] = 0ull;

    uint32_t sbase = (uint32_t)__cvta_generic_to_shared(tile);

    auto issue = [&](int j0, int buf) {
        uint32_t dst = sbase + (uint32_t)buf * (KT * P * 4);
        for (int u = tid; u < KT * 32; u += NTHREADS) {   // 2048 float4 units
            int row = u >> 5, seg = u & 31;
            int gr = j0 + row;
            const float4* src = reinterpret_cast<const float4*>(x);
            int sz = 0;
            if (gr < n) {
                src = reinterpret_cast<const float4*>(x)
                      + (size_t)idx[gr] * 32 + seg;
                sz = 16;
            }
            cp16(dst + (uint32_t)(row * P + seg * 4) * 4, src, sz);
        }
        cp_commit();
    };

    int j0 = blockIdx.x * KT;
    if (j0 < n) {
        issue(j0, 0);
        int buf = 0;
        for (; j0 < n; ) {
            int jn = j0 + stride;
            if (jn < n) { issue(jn, buf ^ 1); cp_wait1(); }
            else cp_wait0();
            __syncthreads();

            if (tid < NT_ACT) {
                const float* tb = tile + buf * (KT * P);
#pragma unroll 2
                for (int k = 0; k < KT; k++) {
                    const float* rowk = tb + k * P;
                    float4 a0 = *reinterpret_cast<const float4*>(rowk + tr * 8);
                    float4 a1 = *reinterpret_cast<const float4*>(rowk + tr * 8 + 4);
                    ulonglong2 b0 = *reinterpret_cast<const ulonglong2*>(rowk + tc * 8);
                    ulonglong2 b1 = *reinterpret_cast<const ulonglong2*>(rowk + tc * 8 + 4);
                    unsigned long long ad[8];
                    ad[0] = dup2(a0.x); ad[1] = dup2(a0.y);
                    ad[2] = dup2(a0.z); ad[3] = dup2(a0.w);
                    ad[4] = dup2(a1.x); ad[5] = dup2(a1.y);
                    ad[6] = dup2(a1.z); ad[7] = dup2(a1.w);
#pragma unroll
                    for (int r = 0; r < 8; r++) {
                        fma2(acc[r][0], ad[r], b0.x);
                        fma2(acc[r][1], ad[r], b0.y);
                        fma2(acc[r][2], ad[r], b1.x);
                        fma2(acc[r][3], ad[r], b1.y);
                    }
                }
            }
            __syncthreads();
            buf ^= 1;
            j0 = jn;
        }
    }

    // write lower-triangle tiles only
    if (tid < NT_ACT) {
        float* out = d_part[c * BPC + blockIdx.x];
#pragma unroll
        for (int r = 0; r < 8; r++) {
#pragma unroll
            for (int p = 0; p < 4; p++)
                *reinterpret_cast<unsigned long long*>(
                    &out[(tr * 8 + r) * P + tc * 8 + p * 2]) = acc[r][p];
        }
    }
}

// ---------------- deterministic reduction + mirror (double accumulation) ----
// One thread per (class, row, 4-col group) in the lower triangle; 29
// independent float4 loads (MLP), double sums, writes value + mirror.
__global__ void reduce_kernel() {
    int e = blockIdx.x * 256 + threadIdx.x;
    if (e >= K_CLS * P * 32) return;
    int c = e >> 12;
    int rem = e & 4095;
    int r = rem >> 5, c4 = rem & 31;
    if (c4 * 4 > r) return;                 // 4-col groups never straddle 8-col tiles

    double s0 = 0.0, s1 = 0.0, s2 = 0.0, s3 = 0.0;
    int off = r * P + c4 * 4;
#pragma unroll
    for (int b = 0; b < BPC; b++) {
        float4 v = *reinterpret_cast<const float4*>(&d_part[c * BPC + b][off]);
        s0 += v.x; s1 += v.y; s2 += v.z; s3 += v.w;
    }
    float4 o = make_float4((float)s0, (float)s1, (float)s2, (float)s3);
    float* cov = d_cov + c * P * P;
    *reinterpret_cast<float4*>(&cov[off]) = o;
    int cb = c4 * 4;
    if (cb + 0 < r) cov[(cb + 0) * P + r] = o.x;
    if (cb + 1 < r) cov[(cb + 1) * P + r] = o.y;
    if (cb + 2 < r) cov[(cb + 2) * P + r] = o.z;
    if (cb + 3 < r) cov[(cb + 3) * P + r] = o.w;
}

// ---------------- Cholesky logdet, 2 columns per barrier pair ---------------
__global__ void chol_kernel(int m) {
    extern __shared__ float A[];  // 128*128 floats = 64 KB
    __shared__ float sd[3];
    int b = blockIdx.x;
    int i = threadIdx.x;          // thread == row

    if (b == 0) {
        float scal = (float)P / ((float)m * EPS_C);
        for (int e = i; e < P * P; e += 128) {
            float v = 0.f;
#pragma unroll
            for (int c = 0; c < K_CLS; c++) v += d_cov[c * P * P + e];
            A[e] = ((e % (P + 1)) == 0 ? 1.0f : 0.0f) + scal * v;
        }
    } else {
        int c = b - 1;
        int n = d_cursor[c];
        int ns = n > 0 ? n : 1;
        float scal = (float)P / ((float)ns * EPS_C);
        for (int e = i; e < P * P; e += 128)
            A[e] = ((e % (P + 1)) == 0 ? 1.0f : 0.0f) + scal * d_cov[c * P * P + e];
    }
    __syncthreads();

    float logsum = 0.0f;
    for (int j = 0; j < P; j += 2) {
        float s0 = 0.0f, s1 = 0.0f;
        if (i >= j) {
            s0 = A[j * P + i];
            s1 = A[(j + 1) * P + i];
            float a00 = 0.f, a01 = 0.f, a10 = 0.f, a11 = 0.f;
            int t = 0;
            for (; t + 1 < j; t += 2) {
                float u0 = A[t * P + i], u1 = A[(t + 1) * P + i];
                a00 += u0 * A[t * P + j];
                a01 += u1 * A[(t + 1) * P + j];
                a10 += u0 * A[t * P + j + 1];
                a11 += u1 * A[(t + 1) * P + j + 1];
            }
            if (t < j) {
                float u = A[t * P + i];
                a00 += u * A[t * P + j];
                a10 += u * A[t * P + j + 1];
            }
            s0 -= a00 + a01;
            s1 -= a10 + a11;
            if (i == j) sd[0] = s0;
            if (i == j + 1) { sd[1] = s0; sd[2] = s1; }
        }
        __syncthreads();
        float d0 = sqrtf(sd[0]);
        float Lj1 = sd[1] / d0;
        float d1 = sqrtf(sd[2] - Lj1 * Lj1);
        logsum += logf(d0) + logf(d1);
        if (i == j) {
            A[j * P + i] = d0;
        } else if (i == j + 1) {
            A[j * P + i] = Lj1;
            A[(j + 1) * P + i] = d1;
        } else if (i > j + 1) {
            float L0 = s0 / d0;
            A[j * P + i] = L0;
            A[(j + 1) * P + i] = (s1 - L0 * Lj1) / d1;
        }
        __syncthreads();
    }
    if (i == 0) d_logdets[b] = logsum;   // = slogdet/2
}

// ---------------- final reduction to 4 scalars ----------------
__global__ void finalize_kernel(float* __restrict__ out, int m) {
    if (threadIdx.x == 0 && blockIdx.x == 0) {
        float disc = d_logdets[0];   // discrimn_empi == discrimn_theo (GAM1 = 1)
        float comp = 0.0f;
#pragma unroll
        for (int c = 0; c < K_CLS; c++) {
            int n = d_cursor[c];
            if (n > 0) comp += d_logdets[1 + c] * ((float)n / (float)m);
        }
        out[0] = -disc + comp;  // GAM2 = 1
        out[1] = disc;
        out[2] = disc;
        out[3] = comp;
    }
}

// ---------------- launch ----------------
extern "C" void kernel_launch(void* const* d_in, const int* in_sizes, int n_in,
                              void* d_out, int out_size) {
    const float* x = (const float*)d_in[0];
    const int*   y = (const int*)d_in[1];
    int m = in_sizes[0] / P;

    cudaFuncSetAttribute(gram_kernel,
                         cudaFuncAttributeMaxDynamicSharedMemorySize, 2 * KT * P * 4);
    cudaFuncSetAttribute(chol_kernel,
                         cudaFuncAttributeMaxDynamicSharedMemorySize, 65536);

    zero_kernel<<<1, 32>>>();
    scatter_kernel<<<(m + 255) / 256, 256>>>(y, m);
    gram_kernel<<<dim3(BPC, K_CLS), NTHREADS, 2 * KT * P * 4>>>(x);
    reduce_kernel<<<(K_CLS * P * 32 + 255) / 256, 256>>>();
    chol_kernel<<<K_CLS + 1, P, 65536>>>(m);
    finalize_kernel<<<1, 32>>>((float*)d_out, m);
}

// round 13
// speedup vs baseline: 1.5624x; 1.0021x over previous
#include <cuda_runtime.h>
#include <cuda_bf16.h>
#include <cstdint>

#define K_CLS 10
#define P 128
#define CAP 262144          // max rows (m)
#define EPS_C 0.01f
#define KT 64               // rows per gram tile
#define BPC 43              // blocks per class (430 blocks -> ~3 per SM)
#define NTHREADS 160        // gram block size (136 compute + loaders)
#define NT_ACT 136          // lower-triangle 8x8 tiles of 16x16 grid

// ---------------- device globals (no allocations allowed) ----------------
__device__ int   d_cursor[K_CLS];              // per-class counts / cursors
__device__ int   d_idx[K_CLS * CAP];           // per-class row index lists
__device__ float d_part[K_CLS * BPC][P * P];   // per-block Gram partials (lower tiles)
__device__ float d_cov[K_CLS * P * P];         // per-class Gram (full, mirrored)
__device__ float d_logdets[K_CLS + 1];         // [0]=full, [1..10]=classes

// ---------------- packed f32x2 helpers ----------------
__device__ __forceinline__ void fma2(unsigned long long& d,
                                     unsigned long long a,
                                     unsigned long long b) {
    asm("fma.rn.f32x2 %0, %1, %2, %0;" : "+l"(d) : "l"(a), "l"(b));
}
__device__ __forceinline__ unsigned long long dup2(float x) {
    unsigned long long r;
    asm("mov.b64 %0, {%1, %1};" : "=l"(r) : "f"(x));
    return r;
}
__device__ __forceinline__ void cp16(uint32_t saddr, const void* gaddr, int sz) {
    asm volatile("cp.async.cg.shared.global [%0], [%1], 16, %2;"
                 :: "r"(saddr), "l"(gaddr), "r"(sz));
}
__device__ __forceinline__ void cp_commit() { asm volatile("cp.async.commit_group;"); }
__device__ __forceinline__ void cp_wait1()  { asm volatile("cp.async.wait_group 1;"); }
__device__ __forceinline__ void cp_wait0()  { asm volatile("cp.async.wait_group 0;"); }

// ---------------- zero small state ----------------
__global__ void zero_kernel() {
    int t = threadIdx.x;
    if (t < K_CLS) d_cursor[t] = 0;
    if (t < K_CLS + 1) d_logdets[t] = 0.0f;
}

// ---------------- class-partition scatter (index lists + counts) ----------------
__global__ void scatter_kernel(const int* __restrict__ y, int m) {
    __shared__ int sCnt[K_CLS], sBase[K_CLS];
    int tid = threadIdx.x;
    int i = blockIdx.x * blockDim.x + tid;
    if (tid < K_CLS) sCnt[tid] = 0;
    __syncthreads();

    int c = 0, local = 0;
    bool act = (i < m);
    if (act) {
        c = y[i];
        c = min(max(c, 0), K_CLS - 1);
        unsigned mask = __match_any_sync(__activemask(), c);
        int leader = __ffs(mask) - 1;
        int lane = tid & 31;
        int rank = __popc(mask & ((1u << lane) - 1));
        int wb = 0;
        if (lane == leader) wb = atomicAdd(&sCnt[c], __popc(mask));
        wb = __shfl_sync(mask, wb, leader);
        local = wb + rank;
    }
    __syncthreads();
    if (tid < K_CLS) sBase[tid] = atomicAdd(&d_cursor[tid], sCnt[tid]);
    __syncthreads();
    if (act) d_idx[c * CAP + sBase[c] + local] = i;
}

// ---------------- exact fp32 Gram, symmetric (lower triangle only) ----------
// 160 threads; threads 0..135 each own one 8x8 micro-tile of the lower
// triangle. f32x2 accumulators, KT=64 smem tile, cp.async double-buffer,
// 3 blocks/SM for latency hiding.
__global__ void __launch_bounds__(NTHREADS, 3)
gram_kernel(const float* __restrict__ x) {
    extern __shared__ float tile[];    // 2 x KT*P floats (64 KB)
    int tid = threadIdx.x;
    int c = blockIdx.y;
    int n = d_cursor[c];
    const int* idx = d_idx + c * CAP;
    const int stride = BPC * KT;

    // map tid -> lower-triangle tile (tr, tc), tc <= tr
    int tr = 0, tc = 0;
    if (tid < NT_ACT) {
        tr = (int)((sqrtf(8.0f * (float)tid + 1.0f) - 1.0f) * 0.5f);
        while ((tr + 1) * (tr + 2) / 2 <= tid) tr++;
        while (tr * (tr + 1) / 2 > tid) tr--;
        tc = tid - tr * (tr + 1) / 2;
    }

    unsigned long long acc[8][4];
#pragma unroll
    for (int r = 0; r < 8; r++)
#pragma unroll
        for (int p = 0; p < 4; p++) acc[r][p] = 0ull;

    uint32_t sbase = (uint32_t)__cvta_generic_to_shared(tile);

    auto issue = [&](int j0, int buf) {
        uint32_t dst = sbase + (uint32_t)buf * (KT * P * 4);
        for (int u = tid; u < KT * 32; u += NTHREADS) {   // 2048 float4 units
            int row = u >> 5, seg = u & 31;
            int gr = j0 + row;
            const float4* src = reinterpret_cast<const float4*>(x);
            int sz = 0;
            if (gr < n) {
                src = reinterpret_cast<const float4*>(x)
                      + (size_t)idx[gr] * 32 + seg;
                sz = 16;
            }
            cp16(dst + (uint32_t)(row * P + seg * 4) * 4, src, sz);
        }
        cp_commit();
    };

    int j0 = blockIdx.x * KT;
    if (j0 < n) {
        issue(j0, 0);
        int buf = 0;
        for (; j0 < n; ) {
            int jn = j0 + stride;
            if (jn < n) { issue(jn, buf ^ 1); cp_wait1(); }
            else cp_wait0();
            __syncthreads();

            if (tid < NT_ACT) {
                const float* tb = tile + buf * (KT * P);
#pragma unroll 2
                for (int k = 0; k < KT; k++) {
                    const float* rowk = tb + k * P;
                    float4 a0 = *reinterpret_cast<const float4*>(rowk + tr * 8);
                    float4 a1 = *reinterpret_cast<const float4*>(rowk + tr * 8 + 4);
                    ulonglong2 b0 = *reinterpret_cast<const ulonglong2*>(rowk + tc * 8);
                    ulonglong2 b1 = *reinterpret_cast<const ulonglong2*>(rowk + tc * 8 + 4);
                    unsigned long long ad[8];
                    ad[0] = dup2(a0.x); ad[1] = dup2(a0.y);
                    ad[2] = dup2(a0.z); ad[3] = dup2(a0.w);
                    ad[4] = dup2(a1.x); ad[5] = dup2(a1.y);
                    ad[6] = dup2(a1.z); ad[7] = dup2(a1.w);
#pragma unroll
                    for (int r = 0; r < 8; r++) {
                        fma2(acc[r][0], ad[r], b0.x);
                        fma2(acc[r][1], ad[r], b0.y);
                        fma2(acc[r][2], ad[r], b1.x);
                        fma2(acc[r][3], ad[r], b1.y);
                    }
                }
            }
            __syncthreads();
            buf ^= 1;
            j0 = jn;
        }
    }

    // write lower-triangle tiles only
    if (tid < NT_ACT) {
        float* out = d_part[c * BPC + blockIdx.x];
#pragma unroll
        for (int r = 0; r < 8; r++) {
#pragma unroll
            for (int p = 0; p < 4; p++)
                *reinterpret_cast<unsigned long long*>(
                    &out[(tr * 8 + r) * P + tc * 8 + p * 2]) = acc[r][p];
        }
    }
}

// ---------------- deterministic reduction + mirror ---------------------------
// One thread per (class, row, lower 4-col group). Sum BPC partials in 4
// buffered chunks (<=11 independent float4 loads live -> real MLP), double
// accumulation, write value + mirror.
__global__ void __launch_bounds__(256, 1) reduce_kernel() {
    int e = blockIdx.x * 256 + threadIdx.x;
    if (e >= K_CLS * P * 32) return;
    int c = e >> 12;
    int rem = e & 4095;
    int r = rem >> 5, c4 = rem & 31;
    if (c4 * 4 > r) return;                 // groups never straddle 8-col tiles

    int off = r * P + c4 * 4;
    double s0 = 0.0, s1 = 0.0, s2 = 0.0, s3 = 0.0;
    const int CH = 11;
#pragma unroll
    for (int base = 0; base < BPC; base += CH) {
        float4 v[CH];
#pragma unroll
        for (int u = 0; u < CH; u++) {
            int b = base + u;
            if (b < BPC)
                v[u] = *reinterpret_cast<const float4*>(&d_part[c * BPC + b][off]);
        }
#pragma unroll
        for (int u = 0; u < CH; u++) {
            int b = base + u;
            if (b < BPC) { s0 += v[u].x; s1 += v[u].y; s2 += v[u].z; s3 += v[u].w; }
        }
    }
    float4 o = make_float4((float)s0, (float)s1, (float)s2, (float)s3);
    float* cov = d_cov + c * P * P;
    *reinterpret_cast<float4*>(&cov[off]) = o;
    int cb = c4 * 4;
    if (cb + 0 < r) cov[(cb + 0) * P + r] = o.x;
    if (cb + 1 < r) cov[(cb + 1) * P + r] = o.y;
    if (cb + 2 < r) cov[(cb + 2) * P + r] = o.z;
    if (cb + 3 < r) cov[(cb + 3) * P + r] = o.w;
}

// ---------------- Cholesky logdet, 2 columns per barrier pair ---------------
__global__ void chol_kernel(int m) {
    extern __shared__ float A[];  // 128*128 floats = 64 KB
    __shared__ float sd[3];
    int b = blockIdx.x;
    int i = threadIdx.x;          // thread == row

    if (b == 0) {
        float scal = (float)P / ((float)m * EPS_C);
        for (int e = i; e < P * P; e += 128) {
            float v = 0.f;
#pragma unroll
            for (int c = 0; c < K_CLS; c++) v += d_cov[c * P * P + e];
            A[e] = ((e % (P + 1)) == 0 ? 1.0f : 0.0f) + scal * v;
        }
    } else {
        int c = b - 1;
        int n = d_cursor[c];
        int ns = n > 0 ? n : 1;
        float scal = (float)P / ((float)ns * EPS_C);
        for (int e = i; e < P * P; e += 128)
            A[e] = ((e % (P + 1)) == 0 ? 1.0f : 0.0f) + scal * d_cov[c * P * P + e];
    }
    __syncthreads();

    float logsum = 0.0f;
    for (int j = 0; j < P; j += 2) {
        float s0 = 0.0f, s1 = 0.0f;
        if (i >= j) {
            s0 = A[j * P + i];
            s1 = A[(j + 1) * P + i];
            float a00 = 0.f, a01 = 0.f, a10 = 0.f, a11 = 0.f;
            int t = 0;
            for (; t + 1 < j; t += 2) {
                float u0 = A[t * P + i], u1 = A[(t + 1) * P + i];
                a00 += u0 * A[t * P + j];
                a01 += u1 * A[(t + 1) * P + j];
                a10 += u0 * A[t * P + j + 1];
                a11 += u1 * A[(t + 1) * P + j + 1];
            }
            if (t < j) {
                float u = A[t * P + i];
                a00 += u * A[t * P + j];
                a10 += u * A[t * P + j + 1];
            }
            s0 -= a00 + a01;
            s1 -= a10 + a11;
            if (i == j) sd[0] = s0;
            if (i == j + 1) { sd[1] = s0; sd[2] = s1; }
        }
        __syncthreads();
        float d0 = sqrtf(sd[0]);
        float Lj1 = sd[1] / d0;
        float d1 = sqrtf(sd[2] - Lj1 * Lj1);
        logsum += logf(d0) + logf(d1);
        if (i == j) {
            A[j * P + i] = d0;
        } else if (i == j + 1) {
            A[j * P + i] = Lj1;
            A[(j + 1) * P + i] = d1;
        } else if (i > j + 1) {
            float L0 = s0 / d0;
            A[j * P + i] = L0;
            A[(j + 1) * P + i] = (s1 - L0 * Lj1) / d1;
        }
        __syncthreads();
    }
    if (i == 0) d_logdets[b] = logsum;   // = slogdet/2
}

// ---------------- final reduction to 4 scalars ----------------
__global__ void finalize_kernel(float* __restrict__ out, int m) {
    if (threadIdx.x == 0 && blockIdx.x == 0) {
        float disc = d_logdets[0];   // discrimn_empi == discrimn_theo (GAM1 = 1)
        float comp = 0.0f;
#pragma unroll
        for (int c = 0; c < K_CLS; c++) {
            int n = d_cursor[c];
            if (n > 0) comp += d_logdets[1 + c] * ((float)n / (float)m);
        }
        out[0] = -disc + comp;  // GAM2 = 1
        out[1] = disc;
        out[2] = disc;
        out[3] = comp;
    }
}

// ---------------- launch ----------------
extern "C" void kernel_launch(void* const* d_in, const int* in_sizes, int n_in,
                              void* d_out, int out_size) {
    const float* x = (const float*)d_in[0];
    const int*   y = (const int*)d_in[1];
    int m = in_sizes[0] / P;

    cudaFuncSetAttribute(gram_kernel,
                         cudaFuncAttributeMaxDynamicSharedMemorySize, 2 * KT * P * 4);
    cudaFuncSetAttribute(chol_kernel,
                         cudaFuncAttributeMaxDynamicSharedMemorySize, 65536);

    zero_kernel<<<1, 32>>>();
    scatter_kernel<<<(m + 255) / 256, 256>>>(y, m);
    gram_kernel<<<dim3(BPC, K_CLS), NTHREADS, 2 * KT * P * 4>>>(x);
    reduce_kernel<<<(K_CLS * P * 32 + 255) / 256, 256>>>();
    chol_kernel<<<K_CLS + 1, P, 65536>>>(m);
    finalize_kernel<<<1, 32>>>((float*)d_out, m);
}

// round 14
// speedup vs baseline: 1.7064x; 1.0922x over previous
#include <cuda_runtime.h>
#include <cuda_bf16.h>
#include <cstdint>

#define K_CLS 10
#define P 128
#define CAP 262144          // max rows (m)
#define EPS_C 0.01f
#define KT 64               // rows per gram tile
#define BPC 43              // blocks per class (430 blocks -> ~3 per SM)
#define NTHREADS 160        // gram block size (136 compute + loaders)
#define NT_ACT 136          // lower-triangle 8x8 tiles of 16x16 grid
#define NGRP 2112           // lower-triangle float4 groups per class

// ---------------- device globals (no allocations allowed) ----------------
__device__ int   d_cursor[K_CLS];              // per-class counts / cursors
__device__ int   d_idx[K_CLS * CAP];           // per-class row index lists
__device__ float d_part[K_CLS * BPC][P * P];   // per-block Gram partials (lower tiles)
__device__ float d_cov[K_CLS * P * P];         // per-class Gram (full, mirrored)
__device__ float d_logdets[K_CLS + 1];         // [0]=full, [1..10]=classes

// ---------------- packed f32x2 helpers ----------------
__device__ __forceinline__ void fma2(unsigned long long& d,
                                     unsigned long long a,
                                     unsigned long long b) {
    asm("fma.rn.f32x2 %0, %1, %2, %0;" : "+l"(d) : "l"(a), "l"(b));
}
__device__ __forceinline__ unsigned long long dup2(float x) {
    unsigned long long r;
    asm("mov.b64 %0, {%1, %1};" : "=l"(r) : "f"(x));
    return r;
}
__device__ __forceinline__ void cp16(uint32_t saddr, const void* gaddr, int sz) {
    asm volatile("cp.async.cg.shared.global [%0], [%1], 16, %2;"
                 :: "r"(saddr), "l"(gaddr), "r"(sz));
}
__device__ __forceinline__ void cp_commit() { asm volatile("cp.async.commit_group;"); }
__device__ __forceinline__ void cp_wait1()  { asm volatile("cp.async.wait_group 1;"); }
__device__ __forceinline__ void cp_wait0()  { asm volatile("cp.async.wait_group 0;"); }

// ---------------- zero small state ----------------
__global__ void zero_kernel() {
    int t = threadIdx.x;
    if (t < K_CLS) d_cursor[t] = 0;
    if (t < K_CLS + 1) d_logdets[t] = 0.0f;
}

// ---------------- class-partition scatter (index lists + counts) ----------------
__global__ void scatter_kernel(const int* __restrict__ y, int m) {
    __shared__ int sCnt[K_CLS], sBase[K_CLS];
    int tid = threadIdx.x;
    int i = blockIdx.x * blockDim.x + tid;
    if (tid < K_CLS) sCnt[tid] = 0;
    __syncthreads();

    int c = 0, local = 0;
    bool act = (i < m);
    if (act) {
        c = y[i];
        c = min(max(c, 0), K_CLS - 1);
        unsigned mask = __match_any_sync(__activemask(), c);
        int leader = __ffs(mask) - 1;
        int lane = tid & 31;
        int rank = __popc(mask & ((1u << lane) - 1));
        int wb = 0;
        if (lane == leader) wb = atomicAdd(&sCnt[c], __popc(mask));
        wb = __shfl_sync(mask, wb, leader);
        local = wb + rank;
    }
    __syncthreads();
    if (tid < K_CLS) sBase[tid] = atomicAdd(&d_cursor[tid], sCnt[tid]);
    __syncthreads();
    if (act) d_idx[c * CAP + sBase[c] + local] = i;
}

// ---------------- exact fp32 Gram, symmetric (lower triangle only) ----------
// 160 threads; threads 0..135 each own one 8x8 micro-tile of the lower
// triangle. f32x2 accumulators, KT=64 smem tile, cp.async double-buffer,
// 3 blocks/SM for latency hiding.
__global__ void __launch_bounds__(NTHREADS, 3)
gram_kernel(const float* __restrict__ x) {
    extern __shared__ float tile[];    // 2 x KT*P floats (64 KB)
    int tid = threadIdx.x;
    int c = blockIdx.y;
    int n = d_cursor[c];
    const int* idx = d_idx + c * CAP;
    const int stride = BPC * KT;

    // map tid -> lower-triangle tile (tr, tc), tc <= tr
    int tr = 0, tc = 0;
    if (tid < NT_ACT) {
        tr = (int)((sqrtf(8.0f * (float)tid + 1.0f) - 1.0f) * 0.5f);
        while ((tr + 1) * (tr + 2) / 2 <= tid) tr++;
        while (tr * (tr + 1) / 2 > tid) tr--;
        tc = tid - tr * (tr + 1) / 2;
    }

    unsigned long long acc[8][4];
#pragma unroll
    for (int r = 0; r < 8; r++)
#pragma unroll
        for (int p = 0; p < 4; p++) acc[r][p] = 0ull;

    uint32_t sbase = (uint32_t)__cvta_generic_to_shared(tile);

    auto issue = [&](int j0, int buf) {
        uint32_t dst = sbase + (uint32_t)buf * (KT * P * 4);
        for (int u = tid; u < KT * 32; u += NTHREADS) {   // 2048 float4 units
            int row = u >> 5, seg = u & 31;
            int gr = j0 + row;
            const float4* src = reinterpret_cast<const float4*>(x);
            int sz = 0;
            if (gr < n) {
                src = reinterpret_cast<const float4*>(x)
                      + (size_t)idx[gr] * 32 + seg;
                sz = 16;
            }
            cp16(dst + (uint32_t)(row * P + seg * 4) * 4, src, sz);
        }
        cp_commit();
    };

    int j0 = blockIdx.x * KT;
    if (j0 < n) {
        issue(j0, 0);
        int buf = 0;
        for (; j0 < n; ) {
            int jn = j0 + stride;
            if (jn < n) { issue(jn, buf ^ 1); cp_wait1(); }
            else cp_wait0();
            __syncthreads();

            if (tid < NT_ACT) {
                const float* tb = tile + buf * (KT * P);
#pragma unroll 2
                for (int k = 0; k < KT; k++) {
                    const float* rowk = tb + k * P;
                    float4 a0 = *reinterpret_cast<const float4*>(rowk + tr * 8);
                    float4 a1 = *reinterpret_cast<const float4*>(rowk + tr * 8 + 4);
                    ulonglong2 b0 = *reinterpret_cast<const ulonglong2*>(rowk + tc * 8);
                    ulonglong2 b1 = *reinterpret_cast<const ulonglong2*>(rowk + tc * 8 + 4);
                    unsigned long long ad[8];
                    ad[0] = dup2(a0.x); ad[1] = dup2(a0.y);
                    ad[2] = dup2(a0.z); ad[3] = dup2(a0.w);
                    ad[4] = dup2(a1.x); ad[5] = dup2(a1.y);
                    ad[6] = dup2(a1.z); ad[7] = dup2(a1.w);
#pragma unroll
                    for (int r = 0; r < 8; r++) {
                        fma2(acc[r][0], ad[r], b0.x);
                        fma2(acc[r][1], ad[r], b0.y);
                        fma2(acc[r][2], ad[r], b1.x);
                        fma2(acc[r][3], ad[r], b1.y);
                    }
                }
            }
            __syncthreads();
            buf ^= 1;
            j0 = jn;
        }
    }

    // write lower-triangle tiles only
    if (tid < NT_ACT) {
        float* out = d_part[c * BPC + blockIdx.x];
#pragma unroll
        for (int r = 0; r < 8; r++) {
#pragma unroll
            for (int p = 0; p < 4; p++)
                *reinterpret_cast<unsigned long long*>(
                    &out[(tr * 8 + r) * P + tc * 8 + p * 2]) = acc[r][p];
        }
    }
}

// ---------------- deterministic reduction + mirror, quad-parallel -----------
// 4 threads per lower-triangle float4 group: thread q sums partials
// b = q, q+4, ... (double), then quad combines via shfl in fixed order.
// Group index inverted via S(r) = r + 2a(a-1) + a*b (r = 4a+b).
__device__ __forceinline__ int Sfun(int rr) {
    int a = rr >> 2, bb = rr & 3;
    return rr + 2 * a * (a - 1) + a * bb;
}
__global__ void __launch_bounds__(256) reduce_kernel() {
    int t = blockIdx.x * 256 + threadIdx.x;
    int quad = t >> 2;
    int q = t & 3;
    bool act = (quad < K_CLS * NGRP);
    int c = 0, g = 0;
    if (act) { c = quad / NGRP; g = quad % NGRP; }

    int r = (int)sqrtf(8.0f * (float)g);
    if (r > 127) r = 127;
    while (r > 0 && Sfun(r) > g) r--;
    while (r < 127 && Sfun(r + 1) <= g) r++;
    int c4 = g - Sfun(r);
    int off = r * P + c4 * 4;

    double s0 = 0.0, s1 = 0.0, s2 = 0.0, s3 = 0.0;
    if (act) {
        for (int b = q; b < BPC; b += 4) {
            float4 v = *reinterpret_cast<const float4*>(&d_part[c * BPC + b][off]);
            s0 += v.x; s1 += v.y; s2 += v.z; s3 += v.w;
        }
    }
    // quad combine (fixed order: (q0+q1) + (q2+q3) pieces)
    const unsigned FULL = 0xFFFFFFFFu;
    s0 += __shfl_down_sync(FULL, s0, 1);
    s1 += __shfl_down_sync(FULL, s1, 1);
    s2 += __shfl_down_sync(FULL, s2, 1);
    s3 += __shfl_down_sync(FULL, s3, 1);
    s0 += __shfl_down_sync(FULL, s0, 2);
    s1 += __shfl_down_sync(FULL, s1, 2);
    s2 += __shfl_down_sync(FULL, s2, 2);
    s3 += __shfl_down_sync(FULL, s3, 2);

    if (act && q == 0) {
        float4 o = make_float4((float)s0, (float)s1, (float)s2, (float)s3);
        float* cov = d_cov + c * P * P;
        *reinterpret_cast<float4*>(&cov[off]) = o;
        int cb = c4 * 4;
        if (cb + 0 < r) cov[(cb + 0) * P + r] = o.x;
        if (cb + 1 < r) cov[(cb + 1) * P + r] = o.y;
        if (cb + 2 < r) cov[(cb + 2) * P + r] = o.z;
        if (cb + 3 < r) cov[(cb + 3) * P + r] = o.w;
    }
}

// ---------------- Cholesky logdet, 2 columns per barrier pair ---------------
__global__ void chol_kernel(int m) {
    extern __shared__ float A[];  // 128*128 floats = 64 KB
    __shared__ float sd[3];
    int b = blockIdx.x;
    int i = threadIdx.x;          // thread == row

    if (b == 0) {
        float scal = (float)P / ((float)m * EPS_C);
        for (int e = i; e < P * P; e += 128) {
            float v = 0.f;
#pragma unroll
            for (int c = 0; c < K_CLS; c++) v += d_cov[c * P * P + e];
            A[e] = ((e % (P + 1)) == 0 ? 1.0f : 0.0f) + scal * v;
        }
    } else {
        int c = b - 1;
        int n = d_cursor[c];
        int ns = n > 0 ? n : 1;
        float scal = (float)P / ((float)ns * EPS_C);
        for (int e = i; e < P * P; e += 128)
            A[e] = ((e % (P + 1)) == 0 ? 1.0f : 0.0f) + scal * d_cov[c * P * P + e];
    }
    __syncthreads();

    float logsum = 0.0f;
    for (int j = 0; j < P; j += 2) {
        float s0 = 0.0f, s1 = 0.0f;
        if (i >= j) {
            s0 = A[j * P + i];
            s1 = A[(j + 1) * P + i];
            float a00 = 0.f, a01 = 0.f, a10 = 0.f, a11 = 0.f;
            int t = 0;
            for (; t + 1 < j; t += 2) {
                float u0 = A[t * P + i], u1 = A[(t + 1) * P + i];
                a00 += u0 * A[t * P + j];
                a01 += u1 * A[(t + 1) * P + j];
                a10 += u0 * A[t * P + j + 1];
                a11 += u1 * A[(t + 1) * P + j + 1];
            }
            if (t < j) {
                float u = A[t * P + i];
                a00 += u * A[t * P + j];
                a10 += u * A[t * P + j + 1];
            }
            s0 -= a00 + a01;
            s1 -= a10 + a11;
            if (i == j) sd[0] = s0;
            if (i == j + 1) { sd[1] = s0; sd[2] = s1; }
        }
        __syncthreads();
        float d0 = sqrtf(sd[0]);
        float Lj1 = sd[1] / d0;
        float d1 = sqrtf(sd[2] - Lj1 * Lj1);
        logsum += logf(d0) + logf(d1);
        if (i == j) {
            A[j * P + i] = d0;
        } else if (i == j + 1) {
            A[j * P + i] = Lj1;
            A[(j + 1) * P + i] = d1;
        } else if (i > j + 1) {
            float L0 = s0 / d0;
            A[j * P + i] = L0;
            A[(j + 1) * P + i] = (s1 - L0 * Lj1) / d1;
        }
        __syncthreads();
    }
    if (i == 0) d_logdets[b] = logsum;   // = slogdet/2
}

// ---------------- final reduction to 4 scalars ----------------
__global__ void finalize_kernel(float* __restrict__ out, int m) {
    if (threadIdx.x == 0 && blockIdx.x == 0) {
        float disc = d_logdets[0];   // discrimn_empi == discrimn_theo (GAM1 = 1)
        float comp = 0.0f;
#pragma unroll
        for (int c = 0; c < K_CLS; c++) {
            int n = d_cursor[c];
            if (n > 0) comp += d_logdets[1 + c] * ((float)n / (float)m);
        }
        out[0] = -disc + comp;  // GAM2 = 1
        out[1] = disc;
        out[2] = disc;
        out[3] = comp;
    }
}

// ---------------- launch ----------------
extern "C" void kernel_launch(void* const* d_in, const int* in_sizes, int n_in,
                              void* d_out, int out_size) {
    const float* x = (const float*)d_in[0];
    const int*   y = (const int*)d_in[1];
    int m = in_sizes[0] / P;

    cudaFuncSetAttribute(gram_kernel,
                         cudaFuncAttributeMaxDynamicSharedMemorySize, 2 * KT * P * 4);
    cudaFuncSetAttribute(chol_kernel,
                         cudaFuncAttributeMaxDynamicSharedMemorySize, 65536);

    zero_kernel<<<1, 32>>>();
    scatter_kernel<<<(m + 255) / 256, 256>>>(y, m);
    gram_kernel<<<dim3(BPC, K_CLS), NTHREADS, 2 * KT * P * 4>>>(x);
    reduce_kernel<<<(K_CLS * NGRP * 4 + 255) / 256, 256>>>();
    chol_kernel<<<K_CLS + 1, P, 65536>>>(m);
    finalize_kernel<<<1, 32>>>((float*)d_out, m);
}

// round 15
// speedup vs baseline: 1.7575x; 1.0299x over previous
#include <cuda_runtime.h>
#include <cuda_bf16.h>
#include <cstdint>

#define K_CLS 10
#define P 128
#define CAP 262144          // max rows (m)
#define EPS_C 0.01f
#define KT 64               // rows per gram tile
#define BPC 43              // blocks per class (430 blocks -> ~3 per SM)
#define BPCP 44             // padded partial count (16B alignment; slot 43 = 0)
#define NTHREADS 160        // gram block size
#define NGRP2 8192          // float2 groups per class (full 128x64 grid)

// ---------------- device globals (no allocations allowed) ----------------
__device__ int   d_cursor[K_CLS];              // per-class counts / cursors
__device__ int   d_idx[K_CLS * CAP];           // per-class row index lists
// partials: [class][group g2 = row*64 + paircol][BPCP] float2 -> coalesced reduce
__device__ float d_part2[(size_t)K_CLS * NGRP2 * BPCP * 2];
__device__ float d_cov[K_CLS * P * P];         // per-class Gram (full, mirrored)
__device__ float d_logdets[K_CLS + 1];         // [0]=full, [1..10]=classes

// ---------------- packed f32x2 helpers ----------------
__device__ __forceinline__ void fma2(unsigned long long& d,
                                     unsigned long long a,
                                     unsigned long long b) {
    asm("fma.rn.f32x2 %0, %1, %2, %0;" : "+l"(d) : "l"(a), "l"(b));
}
__device__ __forceinline__ unsigned long long dup2(float x) {
    unsigned long long r;
    asm("mov.b64 %0, {%1, %1};" : "=l"(r) : "f"(x));
    return r;
}
__device__ __forceinline__ void cp16(uint32_t saddr, const void* gaddr, int sz) {
    asm volatile("cp.async.cg.shared.global [%0], [%1], 16, %2;"
                 :: "r"(saddr), "l"(gaddr), "r"(sz));
}
__device__ __forceinline__ void cp_commit() { asm volatile("cp.async.commit_group;"); }
__device__ __forceinline__ void cp_wait1()  { asm volatile("cp.async.wait_group 1;"); }
__device__ __forceinline__ void cp_wait0()  { asm volatile("cp.async.wait_group 0;"); }

// ---------------- zero small state + partial pads ----------------
__global__ void zero_kernel() {
    int t = blockIdx.x * 256 + threadIdx.x;
    if (t < K_CLS) d_cursor[t] = 0;
    if (t < K_CLS + 1) d_logdets[t] = 0.0f;
    if (t < K_CLS * NGRP2) {
        // zero pad slot bid=43 of every group
        reinterpret_cast<float2*>(d_part2)[(size_t)t * BPCP + (BPCP - 1)] =
            make_float2(0.f, 0.f);
    }
}

// ---------------- class-partition scatter (index lists + counts) ----------------
__global__ void scatter_kernel(const int* __restrict__ y, int m) {
    __shared__ int sCnt[K_CLS], sBase[K_CLS];
    int tid = threadIdx.x;
    int i = blockIdx.x * blockDim.x + tid;
    if (tid < K_CLS) sCnt[tid] = 0;
    __syncthreads();

    int c = 0, local = 0;
    bool act = (i < m);
    if (act) {
        c = y[i];
        c = min(max(c, 0), K_CLS - 1);
        unsigned mask = __match_any_sync(__activemask(), c);
        int leader = __ffs(mask) - 1;
        int lane = tid & 31;
        int rank = __popc(mask & ((1u << lane) - 1));
        int wb = 0;
        if (lane == leader) wb = atomicAdd(&sCnt[c], __popc(mask));
        wb = __shfl_sync(mask, wb, leader);
        local = wb + rank;
    }
    __syncthreads();
    if (tid < K_CLS) sBase[tid] = atomicAdd(&d_cursor[tid], sCnt[tid]);
    __syncthreads();
    if (act) d_idx[c * CAP + sBase[c] + local] = i;
}

// ---------------- exact fp32 Gram, symmetric lower triangle ------------------
// 160 threads. Units 0..127 (warps 0-3): one 8x8 micro-tile each, full k.
// Units 128..135 (warp 4, tiles (15, 8..15)): each tile k-split across a
// 4-lane quad (lane sub handles k = sub, sub+4, ...), combined via quad shfl.
// Block FMA2 cost: 4*32 + 8 = 136 warp-FMA2 per k (was 160).
__global__ void __launch_bounds__(NTHREADS, 3)
gram_kernel(const float* __restrict__ x) {
    extern __shared__ float tile[];    // 2 x KT*P floats (64 KB)
    int tid = threadIdx.x;
    int c = blockIdx.y;
    int n = d_cursor[c];
    const int* idx = d_idx + c * CAP;
    const int stride = BPC * KT;
    bool isW4 = (tid >= 128);
    int sub = tid & 3;

    // unit -> (tr, tc)
    int unit = isW4 ? (128 + ((tid - 128) >> 2)) : tid;
    int tr = (int)((sqrtf(8.0f * (float)unit + 1.0f) - 1.0f) * 0.5f);
    while ((tr + 1) * (tr + 2) / 2 <= unit) tr++;
    while (tr * (tr + 1) / 2 > unit) tr--;
    int tc = unit - tr * (tr + 1) / 2;

    unsigned long long acc[8][4];
#pragma unroll
    for (int r = 0; r < 8; r++)
#pragma unroll
        for (int p = 0; p < 4; p++) acc[r][p] = 0ull;

    uint32_t sbase = (uint32_t)__cvta_generic_to_shared(tile);

    auto issue = [&](int j0, int buf) {
        uint32_t dst = sbase + (uint32_t)buf * (KT * P * 4);
        for (int u = tid; u < KT * 32; u += NTHREADS) {   // 2048 float4 units
            int row = u >> 5, seg = u & 31;
            int gr = j0 + row;
            const float4* src = reinterpret_cast<const float4*>(x);
            int sz = 0;
            if (gr < n) {
                src = reinterpret_cast<const float4*>(x)
                      + (size_t)idx[gr] * 32 + seg;
                sz = 16;
            }
            cp16(dst + (uint32_t)(row * P + seg * 4) * 4, src, sz);
        }
        cp_commit();
    };

    int j0 = blockIdx.x * KT;
    if (j0 < n) {
        issue(j0, 0);
        int buf = 0;
        for (; j0 < n; ) {
            int jn = j0 + stride;
            if (jn < n) { issue(jn, buf ^ 1); cp_wait1(); }
            else cp_wait0();
            __syncthreads();

            const float* tb = tile + buf * (KT * P);
            if (!isW4) {
#pragma unroll 2
                for (int k = 0; k < KT; k++) {
                    const float* rowk = tb + k * P;
                    float4 a0 = *reinterpret_cast<const float4*>(rowk + tr * 8);
                    float4 a1 = *reinterpret_cast<const float4*>(rowk + tr * 8 + 4);
                    ulonglong2 b0 = *reinterpret_cast<const ulonglong2*>(rowk + tc * 8);
                    ulonglong2 b1 = *reinterpret_cast<const ulonglong2*>(rowk + tc * 8 + 4);
                    unsigned long long ad[8];
                    ad[0] = dup2(a0.x); ad[1] = dup2(a0.y);
                    ad[2] = dup2(a0.z); ad[3] = dup2(a0.w);
                    ad[4] = dup2(a1.x); ad[5] = dup2(a1.y);
                    ad[6] = dup2(a1.z); ad[7] = dup2(a1.w);
#pragma unroll
                    for (int r = 0; r < 8; r++) {
                        fma2(acc[r][0], ad[r], b0.x);
                        fma2(acc[r][1], ad[r], b0.y);
                        fma2(acc[r][2], ad[r], b1.x);
                        fma2(acc[r][3], ad[r], b1.y);
                    }
                }
            } else {
                // k-split: this lane handles k = sub, sub+4, ... (uniform loop)
#pragma unroll 2
                for (int k = sub; k < KT; k += 4) {
                    const float* rowk = tb + k * P;
                    float4 a0 = *reinterpret_cast<const float4*>(rowk + tr * 8);
                    float4 a1 = *reinterpret_cast<const float4*>(rowk + tr * 8 + 4);
                    ulonglong2 b0 = *reinterpret_cast<const ulonglong2*>(rowk + tc * 8);
                    ulonglong2 b1 = *reinterpret_cast<const ulonglong2*>(rowk + tc * 8 + 4);
                    unsigned long long ad[8];
                    ad[0] = dup2(a0.x); ad[1] = dup2(a0.y);
                    ad[2] = dup2(a0.z); ad[3] = dup2(a0.w);
                    ad[4] = dup2(a1.x); ad[5] = dup2(a1.y);
                    ad[6] = dup2(a1.z); ad[7] = dup2(a1.w);
#pragma unroll
                    for (int r = 0; r < 8; r++) {
                        fma2(acc[r][0], ad[r], b0.x);
                        fma2(acc[r][1], ad[r], b0.y);
                        fma2(acc[r][2], ad[r], b1.x);
                        fma2(acc[r][3], ad[r], b1.y);
                    }
                }
            }
            __syncthreads();
            buf ^= 1;
            j0 = jn;
        }
    }

    // epilogue: store partials to [class][g2][bid] float2 layout
    const unsigned FULL = 0xFFFFFFFFu;
    float2* base = reinterpret_cast<float2*>(d_part2);
    size_t cbase = (size_t)c * NGRP2;
    if (!isW4) {
#pragma unroll
        for (int r = 0; r < 8; r++)
#pragma unroll
            for (int p = 0; p < 4; p++) {
                int g2 = (tr * 8 + r) * 64 + tc * 4 + p;
                *reinterpret_cast<unsigned long long*>(
                    &base[(cbase + g2) * BPCP + blockIdx.x]) = acc[r][p];
            }
    } else {
        // combine quad partitions in fixed order, sub 0 stores
#pragma unroll
        for (int r = 0; r < 8; r++)
#pragma unroll
            for (int p = 0; p < 4; p++) {
                float2 v = *reinterpret_cast<float2*>(&acc[r][p]);
                v.x += __shfl_down_sync(FULL, v.x, 1, 4);
                v.y += __shfl_down_sync(FULL, v.y, 1, 4);
                v.x += __shfl_down_sync(FULL, v.x, 2, 4);
                v.y += __shfl_down_sync(FULL, v.y, 2, 4);
                if (sub == 0) {
                    int g2 = (tr * 8 + r) * 64 + tc * 4 + p;
                    base[(cbase + g2) * BPCP + blockIdx.x] = v;
                }
            }
    }
}

// ---------------- deterministic reduction + mirror, coalesced ---------------
// One thread per (class, g2) lower-triangle float2 group: 22 contiguous
// float4 loads (43 partials + zero pad), double accumulation in bid order.
__global__ void __launch_bounds__(256) reduce_kernel() {
    int t = blockIdx.x * 256 + threadIdx.x;
    if (t >= K_CLS * NGRP2) return;
    int c = t >> 13, g2 = t & (NGRP2 - 1);
    int r = g2 >> 6, pc = g2 & 63;
    if (2 * pc > r) return;                 // lower-triangle groups only

    const float4* src = reinterpret_cast<const float4*>(
        d_part2 + (size_t)t * BPCP * 2);
    double sx = 0.0, sy = 0.0;
#pragma unroll
    for (int j = 0; j < BPCP / 2; j++) {
        float4 v = src[j];
        sx += v.x; sy += v.y;               // bid 2j
        sx += v.z; sy += v.w;               // bid 2j+1
    }
    float ox = (float)sx, oy = (float)sy;
    float* cov = d_cov + c * P * P;
    int col = pc * 2;
    cov[r * P + col] = ox;
    cov[r * P + col + 1] = oy;
    if (col < r)     cov[col * P + r] = ox;
    if (col + 1 < r) cov[(col + 1) * P + r] = oy;
}

// ---------------- Cholesky logdet, 2 columns per barrier pair ---------------
__global__ void chol_kernel(int m) {
    extern __shared__ float A[];  // 128*128 floats = 64 KB
    __shared__ float sd[3];
    int b = blockIdx.x;
    int i = threadIdx.x;          // thread == row

    if (b == 0) {
        float scal = (float)P / ((float)m * EPS_C);
        for (int e = i; e < P * P; e += 128) {
            float v = 0.f;
#pragma unroll
            for (int c = 0; c < K_CLS; c++) v += d_cov[c * P * P + e];
            A[e] = ((e % (P + 1)) == 0 ? 1.0f : 0.0f) + scal * v;
        }
    } else {
        int c = b - 1;
        int n = d_cursor[c];
        int ns = n > 0 ? n : 1;
        float scal = (float)P / ((float)ns * EPS_C);
        for (int e = i; e < P * P; e += 128)
            A[e] = ((e % (P + 1)) == 0 ? 1.0f : 0.0f) + scal * d_cov[c * P * P + e];
    }
    __syncthreads();

    float logsum = 0.0f;
    for (int j = 0; j < P; j += 2) {
        float s0 = 0.0f, s1 = 0.0f;
        if (i >= j) {
            s0 = A[j * P + i];
            s1 = A[(j + 1) * P + i];
            float a00 = 0.f, a01 = 0.f, a10 = 0.f, a11 = 0.f;
            int t = 0;
            for (; t + 1 < j; t += 2) {
                float u0 = A[t * P + i], u1 = A[(t + 1) * P + i];
                a00 += u0 * A[t * P + j];
                a01 += u1 * A[(t + 1) * P + j];
                a10 += u0 * A[t * P + j + 1];
                a11 += u1 * A[(t + 1) * P + j + 1];
            }
            if (t < j) {
                float u = A[t * P + i];
                a00 += u * A[t * P + j];
                a10 += u * A[t * P + j + 1];
            }
            s0 -= a00 + a01;
            s1 -= a10 + a11;
            if (i == j) sd[0] = s0;
            if (i == j + 1) { sd[1] = s0; sd[2] = s1; }
        }
        __syncthreads();
        float d0 = sqrtf(sd[0]);
        float Lj1 = sd[1] / d0;
        float d1 = sqrtf(sd[2] - Lj1 * Lj1);
        logsum += logf(d0) + logf(d1);
        if (i == j) {
            A[j * P + i] = d0;
        } else if (i == j + 1) {
            A[j * P + i] = Lj1;
            A[(j + 1) * P + i] = d1;
        } else if (i > j + 1) {
            float L0 = s0 / d0;
            A[j * P + i] = L0;
            A[(j + 1) * P + i] = (s1 - L0 * Lj1) / d1;
        }
        __syncthreads();
    }
    if (i == 0) d_logdets[b] = logsum;   // = slogdet/2
}

// ---------------- final reduction to 4 scalars ----------------
__global__ void finalize_kernel(float* __restrict__ out, int m) {
    if (threadIdx.x == 0 && blockIdx.x == 0) {
        float disc = d_logdets[0];   // discrimn_empi == discrimn_theo (GAM1 = 1)
        float comp = 0.0f;
#pragma unroll
        for (int c = 0; c < K_CLS; c++) {
            int n = d_cursor[c];
            if (n > 0) comp += d_logdets[1 + c] * ((float)n / (float)m);
        }
        out[0] = -disc + comp;  // GAM2 = 1
        out[1] = disc;
        out[2] = disc;
        out[3] = comp;
    }
}

// ---------------- launch ----------------
extern "C" void kernel_launch(void* const* d_in, const int* in_sizes, int n_in,
                              void* d_out, int out_size) {
    const float* x = (const float*)d_in[0];
    const int*   y = (const int*)d_in[1];
    int m = in_sizes[0] / P;

    cudaFuncSetAttribute(gram_kernel,
                         cudaFuncAttributeMaxDynamicSharedMemorySize, 2 * KT * P * 4);
    cudaFuncSetAttribute(chol_kernel,
                         cudaFuncAttributeMaxDynamicSharedMemorySize, 65536);

    zero_kernel<<<(K_CLS * NGRP2 + 255) / 256, 256>>>();
    scatter_kernel<<<(m + 255) / 256, 256>>>(y, m);
    gram_kernel<<<dim3(BPC, K_CLS), NTHREADS, 2 * KT * P * 4>>>(x);
    reduce_kernel<<<(K_CLS * NGRP2 + 255) / 256, 256>>>();
    chol_kernel<<<K_CLS + 1, P, 65536>>>(m);
    finalize_kernel<<<1, 32>>>((float*)d_out, m);
}

// round 16
// speedup vs baseline: 1.9845x; 1.1292x over previous
#include <cuda_runtime.h>
#include <cuda_bf16.h>
#include <cstdint>

#define K_CLS 10
#define P 128
#define CAP 262144          // max rows (m)
#define EPS_C 0.01f
#define KT 64               // rows per gram tile
#define BPC 43              // blocks per class (430 blocks -> ~3 per SM)
#define NTHREADS 160        // gram block size
#define NLOW 8256           // lower-triangle elements per 128x128 matrix

// ---------------- device globals (no allocations allowed) ----------------
__device__ int    d_cursor[K_CLS];             // per-class counts / cursors
__device__ int    d_idx[K_CLS * CAP];          // per-class row index lists
__device__ float  d_part[K_CLS * BPC][P * P];  // per-block partials (lower tiles)
__device__ float  d_cov[K_CLS * P * P];        // per-class Gram (full, mirrored)
__device__ double d_logdets[K_CLS + 1];        // [0]=full, [1..10]=classes (logdet/2)

// ---------------- packed f32x2 helpers ----------------
__device__ __forceinline__ void fma2(unsigned long long& d,
                                     unsigned long long a,
                                     unsigned long long b) {
    asm("fma.rn.f32x2 %0, %1, %2, %0;" : "+l"(d) : "l"(a), "l"(b));
}
__device__ __forceinline__ unsigned long long dup2(float x) {
    unsigned long long r;
    asm("mov.b64 %0, {%1, %1};" : "=l"(r) : "f"(x));
    return r;
}
__device__ __forceinline__ void cp16(uint32_t saddr, const void* gaddr, int sz) {
    asm volatile("cp.async.cg.shared.global [%0], [%1], 16, %2;"
                 :: "r"(saddr), "l"(gaddr), "r"(sz));
}
__device__ __forceinline__ void cp_commit() { asm volatile("cp.async.commit_group;"); }
__device__ __forceinline__ void cp_wait1()  { asm volatile("cp.async.wait_group 1;"); }
__device__ __forceinline__ void cp_wait0()  { asm volatile("cp.async.wait_group 0;"); }

// ---------------- zero small state ----------------
__global__ void zero_kernel() {
    int t = threadIdx.x;
    if (t < K_CLS) d_cursor[t] = 0;
    if (t < K_CLS + 1) d_logdets[t] = 0.0;
}

// ---------------- class-partition scatter (index lists + counts) ----------------
__global__ void scatter_kernel(const int* __restrict__ y, int m) {
    __shared__ int sCnt[K_CLS], sBase[K_CLS];
    int tid = threadIdx.x;
    int i = blockIdx.x * blockDim.x + tid;
    if (tid < K_CLS) sCnt[tid] = 0;
    __syncthreads();

    int c = 0, local = 0;
    bool act = (i < m);
    if (act) {
        c = y[i];
        c = min(max(c, 0), K_CLS - 1);
        unsigned mask = __match_any_sync(__activemask(), c);
        int leader = __ffs(mask) - 1;
        int lane = tid & 31;
        int rank = __popc(mask & ((1u << lane) - 1));
        int wb = 0;
        if (lane == leader) wb = atomicAdd(&sCnt[c], __popc(mask));
        wb = __shfl_sync(mask, wb, leader);
        local = wb + rank;
    }
    __syncthreads();
    if (tid < K_CLS) sBase[tid] = atomicAdd(&d_cursor[tid], sCnt[tid]);
    __syncthreads();
    if (act) d_idx[c * CAP + sBase[c] + local] = i;
}

// ---------------- exact fp32 Gram, symmetric lower triangle ------------------
// 160 threads. Units 0..127 (warps 0-3): one 8x8 micro-tile, full k.
// Units 128..135 (warp 4): tile k-split across 4-lane quads, quad shfl combine.
__global__ void __launch_bounds__(NTHREADS, 3)
gram_kernel(const float* __restrict__ x) {
    extern __shared__ float tile[];    // 2 x KT*P floats (64 KB)
    int tid = threadIdx.x;
    int c = blockIdx.y;
    int n = d_cursor[c];
    const int* idx = d_idx + c * CAP;
    const int stride = BPC * KT;
    bool isW4 = (tid >= 128);
    int sub = tid & 3;

    int unit = isW4 ? (128 + ((tid - 128) >> 2)) : tid;
    int tr = (int)((sqrtf(8.0f * (float)unit + 1.0f) - 1.0f) * 0.5f);
    while ((tr + 1) * (tr + 2) / 2 <= unit) tr++;
    while (tr * (tr + 1) / 2 > unit) tr--;
    int tc = unit - tr * (tr + 1) / 2;

    unsigned long long acc[8][4];
#pragma unroll
    for (int r = 0; r < 8; r++)
#pragma unroll
        for (int p = 0; p < 4; p++) acc[r][p] = 0ull;

    uint32_t sbase = (uint32_t)__cvta_generic_to_shared(tile);

    auto issue = [&](int j0, int buf) {
        uint32_t dst = sbase + (uint32_t)buf * (KT * P * 4);
        for (int u = tid; u < KT * 32; u += NTHREADS) {
            int row = u >> 5, seg = u & 31;
            int gr = j0 + row;
            const float4* src = reinterpret_cast<const float4*>(x);
            int sz = 0;
            if (gr < n) {
                src = reinterpret_cast<const float4*>(x)
                      + (size_t)idx[gr] * 32 + seg;
                sz = 16;
            }
            cp16(dst + (uint32_t)(row * P + seg * 4) * 4, src, sz);
        }
        cp_commit();
    };

    int j0 = blockIdx.x * KT;
    if (j0 < n) {
        issue(j0, 0);
        int buf = 0;
        for (; j0 < n; ) {
            int jn = j0 + stride;
            if (jn < n) { issue(jn, buf ^ 1); cp_wait1(); }
            else cp_wait0();
            __syncthreads();

            const float* tb = tile + buf * (KT * P);
            if (!isW4) {
#pragma unroll 2
                for (int k = 0; k < KT; k++) {
                    const float* rowk = tb + k * P;
                    float4 a0 = *reinterpret_cast<const float4*>(rowk + tr * 8);
                    float4 a1 = *reinterpret_cast<const float4*>(rowk + tr * 8 + 4);
                    ulonglong2 b0 = *reinterpret_cast<const ulonglong2*>(rowk + tc * 8);
                    ulonglong2 b1 = *reinterpret_cast<const ulonglong2*>(rowk + tc * 8 + 4);
                    unsigned long long ad[8];
                    ad[0] = dup2(a0.x); ad[1] = dup2(a0.y);
                    ad[2] = dup2(a0.z); ad[3] = dup2(a0.w);
                    ad[4] = dup2(a1.x); ad[5] = dup2(a1.y);
                    ad[6] = dup2(a1.z); ad[7] = dup2(a1.w);
#pragma unroll
                    for (int r = 0; r < 8; r++) {
                        fma2(acc[r][0], ad[r], b0.x);
                        fma2(acc[r][1], ad[r], b0.y);
                        fma2(acc[r][2], ad[r], b1.x);
                        fma2(acc[r][3], ad[r], b1.y);
                    }
                }
            } else {
#pragma unroll 2
                for (int k = sub; k < KT; k += 4) {
                    const float* rowk = tb + k * P;
                    float4 a0 = *reinterpret_cast<const float4*>(rowk + tr * 8);
                    float4 a1 = *reinterpret_cast<const float4*>(rowk + tr * 8 + 4);
                    ulonglong2 b0 = *reinterpret_cast<const ulonglong2*>(rowk + tc * 8);
                    ulonglong2 b1 = *reinterpret_cast<const ulonglong2*>(rowk + tc * 8 + 4);
                    unsigned long long ad[8];
                    ad[0] = dup2(a0.x); ad[1] = dup2(a0.y);
                    ad[2] = dup2(a0.z); ad[3] = dup2(a0.w);
                    ad[4] = dup2(a1.x); ad[5] = dup2(a1.y);
                    ad[6] = dup2(a1.z); ad[7] = dup2(a1.w);
#pragma unroll
                    for (int r = 0; r < 8; r++) {
                        fma2(acc[r][0], ad[r], b0.x);
                        fma2(acc[r][1], ad[r], b0.y);
                        fma2(acc[r][2], ad[r], b1.x);
                        fma2(acc[r][3], ad[r], b1.y);
                    }
                }
            }
            __syncthreads();
            buf ^= 1;
            j0 = jn;
        }
    }

    // epilogue: [bid][element] layout (coalesced for the reduce)
    const unsigned FULL = 0xFFFFFFFFu;
    float* out = d_part[c * BPC + blockIdx.x];
    if (!isW4) {
#pragma unroll
        for (int r = 0; r < 8; r++)
#pragma unroll
            for (int p = 0; p < 4; p++)
                *reinterpret_cast<unsigned long long*>(
                    &out[(tr * 8 + r) * P + tc * 8 + p * 2]) = acc[r][p];
    } else {
#pragma unroll
        for (int r = 0; r < 8; r++)
#pragma unroll
            for (int p = 0; p < 4; p++) {
                float2 v = *reinterpret_cast<float2*>(&acc[r][p]);
                v.x += __shfl_down_sync(FULL, v.x, 1, 4);
                v.y += __shfl_down_sync(FULL, v.y, 1, 4);
                v.x += __shfl_down_sync(FULL, v.x, 2, 4);
                v.y += __shfl_down_sync(FULL, v.y, 2, 4);
                if (sub == 0)
                    *reinterpret_cast<float2*>(
                        &out[(tr * 8 + r) * P + tc * 8 + p * 2]) = v;
            }
    }
}

// ---------------- deterministic reduction + mirror, element-per-thread ------
// One thread per (class, lower-triangle element): 43 independent coalesced
// LDG.32 (consecutive threads -> consecutive addresses), double sum in order.
__global__ void __launch_bounds__(256) reduce_kernel() {
    int t = blockIdx.x * 256 + threadIdx.x;
    if (t >= K_CLS * NLOW) return;
    int c = t / NLOW, le = t % NLOW;
    int r = (int)((sqrtf(8.0f * (float)le + 1.0f) - 1.0f) * 0.5f);
    while ((r + 1) * (r + 2) / 2 <= le) r++;
    while (r * (r + 1) / 2 > le) r--;
    int col = le - r * (r + 1) / 2;
    int elem = r * P + col;

    float v[BPC];
#pragma unroll
    for (int b = 0; b < BPC; b++) v[b] = d_part[c * BPC + b][elem];
    double s = 0.0;
#pragma unroll
    for (int b = 0; b < BPC; b++) s += (double)v[b];

    float o = (float)s;
    float* cov = d_cov + c * P * P;
    cov[elem] = o;
    if (col < r) cov[col * P + r] = o;
}

// ---------------- Cholesky logdet, 2 cols/barrier, double log reduction -----
__global__ void chol_kernel(int m) {
    extern __shared__ float A[];  // 128*128 floats = 64 KB
    __shared__ float sd[3];
    __shared__ float sDD[P];      // squared diagonals
    __shared__ double sW[4];
    int b = blockIdx.x;
    int i = threadIdx.x;          // thread == row

    if (b == 0) {
        float scal = (float)P / ((float)m * EPS_C);
        for (int e = i; e < P * P; e += 128) {
            float v = 0.f;
#pragma unroll
            for (int c = 0; c < K_CLS; c++) v += d_cov[c * P * P + e];
            A[e] = ((e % (P + 1)) == 0 ? 1.0f : 0.0f) + scal * v;
        }
    } else {
        int c = b - 1;
        int n = d_cursor[c];
        int ns = n > 0 ? n : 1;
        float scal = (float)P / ((float)ns * EPS_C);
        for (int e = i; e < P * P; e += 128)
            A[e] = ((e % (P + 1)) == 0 ? 1.0f : 0.0f) + scal * d_cov[c * P * P + e];
    }
    __syncthreads();

    for (int j = 0; j < P; j += 2) {
        float s0 = 0.0f, s1 = 0.0f;
        if (i >= j) {
            s0 = A[j * P + i];
            s1 = A[(j + 1) * P + i];
            float a00 = 0.f, a01 = 0.f, a10 = 0.f, a11 = 0.f;
            int t = 0;
            for (; t + 1 < j; t += 2) {
                float u0 = A[t * P + i], u1 = A[(t + 1) * P + i];
                a00 += u0 * A[t * P + j];
                a01 += u1 * A[(t + 1) * P + j];
                a10 += u0 * A[t * P + j + 1];
                a11 += u1 * A[(t + 1) * P + j + 1];
            }
            if (t < j) {
                float u = A[t * P + i];
                a00 += u * A[t * P + j];
                a10 += u * A[t * P + j + 1];
            }
            s0 -= a00 + a01;
            s1 -= a10 + a11;
            if (i == j) sd[0] = s0;
            if (i == j + 1) { sd[1] = s0; sd[2] = s1; }
        }
        __syncthreads();
        float dd0 = sd[0];
        float d0 = sqrtf(dd0);
        float Lj1 = sd[1] / d0;
        float dd1 = sd[2] - Lj1 * Lj1;
        float d1 = sqrtf(dd1);
        if (i == 0) { sDD[j] = dd0; sDD[j + 1] = dd1; }
        if (i == j) {
            A[j * P + i] = d0;
        } else if (i == j + 1) {
            A[j * P + i] = Lj1;
            A[(j + 1) * P + i] = d1;
        } else if (i > j + 1) {
            float L0 = s0 / d0;
            A[j * P + i] = L0;
            A[(j + 1) * P + i] = (s1 - L0 * Lj1) / d1;
        }
        __syncthreads();
    }

    // logdet/2 = 0.5 * sum log(dd), double precision, fixed-order reduction
    double lv = 0.5 * log((double)sDD[i]);
    const unsigned FULL = 0xFFFFFFFFu;
#pragma unroll
    for (int off = 16; off >= 1; off >>= 1)
        lv += __shfl_down_sync(FULL, lv, off);
    if ((i & 31) == 0) sW[i >> 5] = lv;
    __syncthreads();
    if (i == 0)
        d_logdets[b] = (sW[0] + sW[1]) + (sW[2] + sW[3]);
}

// ---------------- final reduction to 4 scalars (double) ----------------
__global__ void finalize_kernel(float* __restrict__ out, int m) {
    if (threadIdx.x == 0 && blockIdx.x == 0) {
        double disc = d_logdets[0];   // discrimn_empi == discrimn_theo (GAM1=1)
        double comp = 0.0;
#pragma unroll
        for (int c = 0; c < K_CLS; c++) {
            int n = d_cursor[c];
            if (n > 0) comp += d_logdets[1 + c] * ((double)n / (double)m);
        }
        out[0] = (float)(-disc + comp);  // GAM2 = 1
        out[1] = (float)disc;
        out[2] = (float)disc;
        out[3] = (float)comp;
    }
}

// ---------------- launch ----------------
extern "C" void kernel_launch(void* const* d_in, const int* in_sizes, int n_in,
                              void* d_out, int out_size) {
    const float* x = (const float*)d_in[0];
    const int*   y = (const int*)d_in[1];
    int m = in_sizes[0] / P;

    cudaFuncSetAttribute(gram_kernel,
                         cudaFuncAttributeMaxDynamicSharedMemorySize, 2 * KT * P * 4);
    cudaFuncSetAttribute(chol_kernel,
                         cudaFuncAttributeMaxDynamicSharedMemorySize, 65536);

    zero_kernel<<<1, 32>>>();
    scatter_kernel<<<(m + 255) / 256, 256>>>(y, m);
    gram_kernel<<<dim3(BPC, K_CLS), NTHREADS, 2 * KT * P * 4>>>(x);
    reduce_kernel<<<(K_CLS * NLOW + 255) / 256, 256>>>();
    chol_kernel<<<K_CLS + 1, P, 65536>>>(m);
    finalize_kernel<<<1, 32>>>((float*)d_out, m);
}